// round 1
// baseline (speedup 1.0000x reference)
#include <cuda_runtime.h>
#include <math.h>

// Problem constants
#define Bdim 16
#define Nn   1024
#define Dd   256
#define Mm   128
#define Cc   8192
#define NEG_SLOPE 0.2f

static const int BND = Bdim * Nn * Dd;          // 4,194,304
static const long BND_L = (long)Bdim * Nn * Dd;

// ---------------- scratch (device globals; no allocation) ----------------
__device__ float g_xp[3 * Bdim * Nn * Dd];      // projected inputs
__device__ float g_h [3 * Bdim * Nn * Dd];      // hypergraph outputs
__device__ float g_Q [3 * Bdim * Nn * Dd];
__device__ float g_Kb[3 * Bdim * Nn * Dd];
__device__ float g_Vb[3 * Bdim * Nn * Dd];
__device__ float g_S [Bdim * Nn * Nn];          // attention scores (reused per pair)
__device__ float g_es[3 * Mm * Bdim * Dd];      // edge_sums
__device__ float g_xe[3 * Mm * Bdim * Dd];      // x_edge
__device__ float g_e [3 * Cc * Bdim];           // logits -> alpha (in place)
__device__ int   g_ncnt[3 * Nn], g_noff[3 * Nn], g_nlist[3 * Cc];
__device__ int   g_ecnt[3 * Mm], g_eoff[3 * Mm], g_elist[3 * Cc];

// ---------------- GEMM: C[M,N] = alpha * A[M,K] @ op(B) (+bias) (+C) -----
// A row-major [M,K]. TRANS_B=false: B is [K,N]. TRANS_B=true: B is [N,K].
// Requires M%128==0, N%128==0, K%16==0 (true for all calls here).
template<bool TRANS_B>
__global__ __launch_bounds__(256)
void gemm_kernel(const float* __restrict__ A, const float* __restrict__ Bg,
                 const float* __restrict__ bias, float* __restrict__ Cg,
                 int Mrows, int Ncols, int Kdim,
                 long sA, long sB, long sC, float alpha, int accum)
{
    const int BM = 128, BN = 128, BK = 16;
    __shared__ float As[BK][BM];
    __shared__ float Bs[BK][BN];

    A  += (long)blockIdx.z * sA;
    Bg += (long)blockIdx.z * sB;
    Cg += (long)blockIdx.z * sC;

    const int i0 = blockIdx.y * BM;
    const int j0 = blockIdx.x * BN;
    const int tid = threadIdx.x;
    const int tx = tid & 15, ty = tid >> 4;

    float acc[8][8];
#pragma unroll
    for (int i = 0; i < 8; i++)
#pragma unroll
        for (int j = 0; j < 8; j++) acc[i][j] = 0.f;

    for (int k0 = 0; k0 < Kdim; k0 += BK) {
        // load A tile (transposed into As[k][i])
#pragma unroll
        for (int q = 0; q < 2; q++) {
            int f = tid + q * 256;          // 0..511 float4 slots
            int row = f >> 2, kc = f & 3;
            float4 v = *(const float4*)&A[(long)(i0 + row) * Kdim + k0 + kc * 4];
            As[kc * 4 + 0][row] = v.x;
            As[kc * 4 + 1][row] = v.y;
            As[kc * 4 + 2][row] = v.z;
            As[kc * 4 + 3][row] = v.w;
        }
        if (TRANS_B) {
#pragma unroll
            for (int q = 0; q < 2; q++) {
                int f = tid + q * 256;
                int row = f >> 2, kc = f & 3;   // row = j index
                float4 v = *(const float4*)&Bg[(long)(j0 + row) * Kdim + k0 + kc * 4];
                Bs[kc * 4 + 0][row] = v.x;
                Bs[kc * 4 + 1][row] = v.y;
                Bs[kc * 4 + 2][row] = v.z;
                Bs[kc * 4 + 3][row] = v.w;
            }
        } else {
#pragma unroll
            for (int q = 0; q < 2; q++) {
                int f = tid + q * 256;
                int kr = f >> 5, jc = f & 31;
                float4 v = *(const float4*)&Bg[(long)(k0 + kr) * Ncols + j0 + jc * 4];
                *(float4*)&Bs[kr][jc * 4] = v;
            }
        }
        __syncthreads();

#pragma unroll
        for (int k = 0; k < BK; k++) {
            float ar[8], br[8];
            *(float4*)&ar[0] = *(const float4*)&As[k][ty * 8];
            *(float4*)&ar[4] = *(const float4*)&As[k][ty * 8 + 4];
            *(float4*)&br[0] = *(const float4*)&Bs[k][tx * 8];
            *(float4*)&br[4] = *(const float4*)&Bs[k][tx * 8 + 4];
#pragma unroll
            for (int ii = 0; ii < 8; ii++)
#pragma unroll
                for (int jj = 0; jj < 8; jj++)
                    acc[ii][jj] += ar[ii] * br[jj];
        }
        __syncthreads();
    }

#pragma unroll
    for (int ii = 0; ii < 8; ii++) {
        long r = i0 + ty * 8 + ii;
#pragma unroll
        for (int jj = 0; jj < 8; jj++) {
            int jc = j0 + tx * 8 + jj;
            float v = acc[ii][jj] * alpha;
            if (bias) v += bias[jc];
            if (accum) v += Cg[r * Ncols + jc];
            Cg[r * Ncols + jc] = v;
        }
    }
}

// ---------------- deterministic CSR build (one block) --------------------
__global__ void build_csr(const int* __restrict__ idx, int* cnt, int* off, int* list)
{
    __shared__ int sidx[Cc];
    __shared__ int sbuf[1024];
    int tid = threadIdx.x;
    for (int i = tid; i < Cc; i += blockDim.x) sidx[i] = idx[i];
    __syncthreads();

    int my = 0;
    for (int c = 0; c < Cc; c++) my += (sidx[c] == tid);
    sbuf[tid] = my;
    __syncthreads();
    for (int o = 1; o < blockDim.x; o <<= 1) {
        int v = (tid >= o) ? sbuf[tid - o] : 0;
        __syncthreads();
        sbuf[tid] += v;
        __syncthreads();
    }
    int start = sbuf[tid] - my;
    cnt[tid] = my;
    off[tid] = start;
    int p = start;
    for (int c = 0; c < Cc; c++)
        if (sidx[c] == tid) list[p++] = c;
}

// ---------------- edge_sums[e,b,:] = sum_{c in edge e} xp[b, node[c], :] --
__global__ void edge_sum_kernel(const float* __restrict__ xp, const int* __restrict__ hidx,
                                const int* __restrict__ ecnt, const int* __restrict__ eoff,
                                const int* __restrict__ elist, float* __restrict__ es)
{
    int e = blockIdx.x, b = blockIdx.y, d = threadIdx.x;
    int cnt = ecnt[e], off = eoff[e];
    float s = 0.f;
    for (int i = 0; i < cnt; i++) {
        int c = elist[off + i];
        int node = hidx[c];
        s += xp[((long)b * Nn + node) * Dd + d];
    }
    es[((long)e * Bdim + b) * Dd + d] = s;
}

// ---------------- attention logits e[c,b] (leaky relu applied) -----------
__global__ void logits_kernel(const float* __restrict__ xp, const float* __restrict__ es,
                              const int* __restrict__ hidx, const float* __restrict__ att,
                              float* __restrict__ e_out)
{
    int c = blockIdx.x;
    int node = hidx[c], edge = hidx[Cc + c];
    __shared__ float satt[2 * Dd];
    int tid = threadIdx.x;
    satt[tid] = att[tid];
    satt[tid + Dd] = att[tid + Dd];
    __syncthreads();

    int w = tid >> 5, lane = tid & 31;
    for (int bb = w; bb < Bdim; bb += 8) {
        float s = 0.f;
#pragma unroll
        for (int i = 0; i < Dd / 32; i++) {
            int d = lane + 32 * i;
            s += xp[((long)bb * Nn + node) * Dd + d] * satt[d]
               + es[((long)edge * Bdim + bb) * Dd + d] * satt[Dd + d];
        }
#pragma unroll
        for (int o = 16; o; o >>= 1) s += __shfl_xor_sync(0xffffffffu, s, o);
        if (lane == 0) {
            float v = (s >= 0.f) ? s : NEG_SLOPE * s;
            e_out[c * Bdim + bb] = v;
        }
    }
}

// ---------------- grouped softmax by node (in place e -> alpha) ----------
__global__ void node_softmax(float* __restrict__ e, const int* __restrict__ ncnt,
                             const int* __restrict__ noff, const int* __restrict__ nlist)
{
    int n = blockIdx.x, b = threadIdx.x;
    if (b >= Bdim) return;
    int cnt = ncnt[n];
    if (!cnt) return;
    int off = noff[n];
    float mx = -1e30f;
    for (int i = 0; i < cnt; i++) {
        int c = nlist[off + i];
        mx = fmaxf(mx, e[c * Bdim + b]);
    }
    float sum = 0.f;
    for (int i = 0; i < cnt; i++) {
        int c = nlist[off + i];
        float v = expf(e[c * Bdim + b] - mx);
        e[c * Bdim + b] = v;
        sum += v;
    }
    float inv = 1.f / (sum + 1e-16f);
    for (int i = 0; i < cnt; i++) {
        int c = nlist[off + i];
        e[c * Bdim + b] *= inv;
    }
}

// ---------------- x_edge[e,b,:] = (1/|e|) sum alpha[c,b]*xp[b,node[c],:] --
__global__ void xedge_kernel(const float* __restrict__ xp, const float* __restrict__ alpha,
                             const int* __restrict__ hidx,
                             const int* __restrict__ ecnt, const int* __restrict__ eoff,
                             const int* __restrict__ elist, float* __restrict__ xe)
{
    int e = blockIdx.x, b = blockIdx.y, d = threadIdx.x;
    int cnt = ecnt[e];
    float s = 0.f;
    if (cnt) {
        int off = eoff[e];
        for (int i = 0; i < cnt; i++) {
            int c = elist[off + i];
            int node = hidx[c];
            s += alpha[c * Bdim + b] * xp[((long)b * Nn + node) * Dd + d];
        }
        s /= (float)cnt;
    }
    xe[((long)e * Bdim + b) * Dd + d] = s;
}

// ---------------- h[b,n,:] = (1/|n|) sum alpha[c,b]*x_edge[edge[c],b,:] ---
__global__ void xnode_kernel(const float* __restrict__ xe, const float* __restrict__ alpha,
                             const int* __restrict__ hidx,
                             const int* __restrict__ ncnt, const int* __restrict__ noff,
                             const int* __restrict__ nlist, float* __restrict__ h)
{
    int n = blockIdx.x, b = blockIdx.y, d = threadIdx.x;
    int cnt = ncnt[n];
    float s = 0.f;
    if (cnt) {
        int off = noff[n];
        for (int i = 0; i < cnt; i++) {
            int c = nlist[off + i];
            int eidx = hidx[Cc + c];
            s += alpha[c * Bdim + b] * xe[((long)eidx * Bdim + b) * Dd + d];
        }
        s /= (float)cnt;
    }
    h[((long)b * Nn + n) * Dd + d] = s;
}

// ---------------- row softmax over 1024-wide rows ------------------------
__global__ void softmax_rows(float* __restrict__ S)
{
    long row = blockIdx.x;
    float* p = S + row * 1024;
    int tid = threadIdx.x;
    float v[4];
    float mx = -1e30f;
#pragma unroll
    for (int i = 0; i < 4; i++) {
        v[i] = p[tid + 256 * i];
        mx = fmaxf(mx, v[i]);
    }
    __shared__ float red[256];
    red[tid] = mx;
    __syncthreads();
    for (int o = 128; o; o >>= 1) {
        if (tid < o) red[tid] = fmaxf(red[tid], red[tid + o]);
        __syncthreads();
    }
    mx = red[0];
    __syncthreads();
    float s = 0.f;
#pragma unroll
    for (int i = 0; i < 4; i++) {
        v[i] = expf(v[i] - mx);
        s += v[i];
    }
    red[tid] = s;
    __syncthreads();
    for (int o = 128; o; o >>= 1) {
        if (tid < o) red[tid] += red[tid + o];
        __syncthreads();
    }
    float inv = 1.f / red[0];
#pragma unroll
    for (int i = 0; i < 4; i++) p[tid + 256 * i] = v[i] * inv;
}

// ---------------- relu -----------------------------------------------------
__global__ void relu_kernel(float* __restrict__ p, long n)
{
    long i = (long)blockIdx.x * blockDim.x + threadIdx.x;
    long stride = (long)gridDim.x * blockDim.x;
    for (; i < n; i += stride) p[i] = fmaxf(p[i], 0.f);
}

// ---------------- launcher -------------------------------------------------
extern "C" void kernel_launch(void* const* d_in, const int* in_sizes, int n_in,
                              void* d_out, int out_size)
{
    const float* x[3]    = {(const float*)d_in[0], (const float*)d_in[1], (const float*)d_in[2]};
    const int*   hidx[3] = {(const int*)d_in[3], (const int*)d_in[4], (const int*)d_in[5]};
    const float* W_hg = (const float*)d_in[6];
    const float* att  = (const float*)d_in[7];
    const float* WQ = (const float*)d_in[8];
    const float* bQ = (const float*)d_in[9];
    const float* WK = (const float*)d_in[10];
    const float* bK = (const float*)d_in[11];
    const float* WV = (const float*)d_in[12];
    const float* bV = (const float*)d_in[13];
    const float* WO = (const float*)d_in[14];
    const float* bO = (const float*)d_in[15];
    float* out = (float*)d_out;

    float *xp, *h, *Q, *Kb, *Vb, *S, *es, *xe, *ealpha;
    int *ncnt, *noff, *nlist, *ecnt, *eoff, *elist;
    cudaGetSymbolAddress((void**)&xp, g_xp);
    cudaGetSymbolAddress((void**)&h,  g_h);
    cudaGetSymbolAddress((void**)&Q,  g_Q);
    cudaGetSymbolAddress((void**)&Kb, g_Kb);
    cudaGetSymbolAddress((void**)&Vb, g_Vb);
    cudaGetSymbolAddress((void**)&S,  g_S);
    cudaGetSymbolAddress((void**)&es, g_es);
    cudaGetSymbolAddress((void**)&xe, g_xe);
    cudaGetSymbolAddress((void**)&ealpha, g_e);
    cudaGetSymbolAddress((void**)&ncnt, g_ncnt);
    cudaGetSymbolAddress((void**)&noff, g_noff);
    cudaGetSymbolAddress((void**)&nlist, g_nlist);
    cudaGetSymbolAddress((void**)&ecnt, g_ecnt);
    cudaGetSymbolAddress((void**)&eoff, g_eoff);
    cudaGetSymbolAddress((void**)&elist, g_elist);

    const long ND = (long)Nn * Dd;       // per-batch stride within a modality
    const long NN2 = (long)Nn * Nn;

    // 1) xp = x @ W_hg  (per modality: [16384,256] @ [256,256])
    for (int m = 0; m < 3; m++)
        gemm_kernel<false><<<dim3(2, 128, 1), 256>>>(
            x[m], W_hg, nullptr, xp + (long)m * BND,
            Bdim * Nn, Dd, Dd, 0, 0, 0, 1.f, 0);

    // 2) CSR by node / by edge (deterministic)
    for (int m = 0; m < 3; m++) {
        build_csr<<<1, Nn>>>(hidx[m],       ncnt + m * Nn, noff + m * Nn, nlist + m * Cc);
        build_csr<<<1, Mm>>>(hidx[m] + Cc,  ecnt + m * Mm, eoff + m * Mm, elist + m * Cc);
    }

    // 3) edge_sums
    for (int m = 0; m < 3; m++)
        edge_sum_kernel<<<dim3(Mm, Bdim), Dd>>>(
            xp + (long)m * BND, hidx[m],
            ecnt + m * Mm, eoff + m * Mm, elist + m * Cc,
            es + (long)m * Mm * Bdim * Dd);

    // 4) logits + leaky relu
    for (int m = 0; m < 3; m++)
        logits_kernel<<<Cc, 256>>>(
            xp + (long)m * BND, es + (long)m * Mm * Bdim * Dd,
            hidx[m], att, ealpha + (long)m * Cc * Bdim);

    // 5) grouped softmax (e -> alpha in place)
    for (int m = 0; m < 3; m++)
        node_softmax<<<Nn, 32>>>(
            ealpha + (long)m * Cc * Bdim,
            ncnt + m * Nn, noff + m * Nn, nlist + m * Cc);

    // 6) x_edge
    for (int m = 0; m < 3; m++)
        xedge_kernel<<<dim3(Mm, Bdim), Dd>>>(
            xp + (long)m * BND, ealpha + (long)m * Cc * Bdim, hidx[m],
            ecnt + m * Mm, eoff + m * Mm, elist + m * Cc,
            xe + (long)m * Mm * Bdim * Dd);

    // 7) x_node -> h (transposed to [B,N,D])
    for (int m = 0; m < 3; m++)
        xnode_kernel<<<dim3(Nn, Bdim), Dd>>>(
            xe + (long)m * Mm * Bdim * Dd, ealpha + (long)m * Cc * Bdim, hidx[m],
            ncnt + m * Nn, noff + m * Nn, nlist + m * Cc,
            h + (long)m * BND);

    // 8) projections over all modalities at once ([49152,256] @ [256,256])
    gemm_kernel<false><<<dim3(2, 384, 1), 256>>>(h, WQ, bQ, Q,  3 * Bdim * Nn, Dd, Dd, 0, 0, 0, 1.f, 0);
    gemm_kernel<false><<<dim3(2, 384, 1), 256>>>(h, WK, bK, Kb, 3 * Bdim * Nn, Dd, Dd, 0, 0, 0, 1.f, 0);
    gemm_kernel<false><<<dim3(2, 384, 1), 256>>>(h, WV, bV, Vb, 3 * Bdim * Nn, Dd, Dd, 0, 0, 0, 1.f, 0);
    // base: out = h @ WO + bO  (msg accumulated into it below)
    gemm_kernel<false><<<dim3(2, 384, 1), 256>>>(h, WO, bO, out, 3 * Bdim * Nn, Dd, Dd, 0, 0, 0, 1.f, 0);

    // 9) cross-modal attention, 6 (m,n) pairs
    const float scale = 0.0625f;   // 1/sqrt(256)
    for (int m = 0; m < 3; m++) {
        for (int n = 0; n < 3; n++) {
            if (n == m) continue;
            // S = scale * Q_m @ K_n^T  (batched over B)
            gemm_kernel<true><<<dim3(8, 8, Bdim), 256>>>(
                Q + (long)m * BND, Kb + (long)n * BND, nullptr, S,
                Nn, Nn, Dd, ND, ND, NN2, scale, 0);
            softmax_rows<<<Bdim * Nn, 256>>>(S);
            // out_m += S @ V_n
            gemm_kernel<false><<<dim3(2, 8, Bdim), 256>>>(
                S, Vb + (long)n * BND, nullptr, out + (long)m * BND,
                Nn, Dd, Nn, NN2, ND, ND, 1.f, 1);
        }
    }

    // 10) final relu
    relu_kernel<<<4096, 256>>>(out, 3L * BND);
}

// round 2
// speedup vs baseline: 1.3370x; 1.3370x over previous
#include <cuda_runtime.h>
#include <math.h>

// Problem constants
#define Bdim 16
#define Nn   1024
#define Dd   256
#define Mm   128
#define Cc   8192
#define NEG_SLOPE 0.2f

static const int BND = Bdim * Nn * Dd;          // 4,194,304

// ---------------- scratch (device globals; no allocation) ----------------
__device__ float g_xp[3 * Bdim * Nn * Dd];      // projected inputs
__device__ float g_h [3 * Bdim * Nn * Dd];      // hypergraph outputs
__device__ float g_Q [3 * Bdim * Nn * Dd];
__device__ float g_Kb[3 * Bdim * Nn * Dd];
__device__ float g_Vb[3 * Bdim * Nn * Dd];
__device__ float g_S [Bdim * Nn * Nn];          // attention scores (reused per pair)
__device__ float g_es[3 * Mm * Bdim * Dd];      // edge_sums
__device__ float g_xe[3 * Mm * Bdim * Dd];      // x_edge
__device__ float g_e [3 * Cc * Bdim];           // logits -> alpha (in place)
__device__ int   g_ncnt[3 * Nn], g_noff[3 * Nn], g_nlist[3 * Cc];
__device__ int   g_ecnt[3 * Mm], g_eoff[3 * Mm], g_elist[3 * Cc];

// ---------------- GEMM: C[M,N] = alpha * A[M,K] @ op(B) (+bias) (+C) -----
// A row-major [M,K]. TRANS_B=false: B is [K,N]. TRANS_B=true: B is [N,K].
// Requires M%128==0, N%128==0, K%16==0 (true for all calls here).
template<bool TRANS_B>
__global__ __launch_bounds__(256)
void gemm_kernel(const float* __restrict__ A, const float* __restrict__ Bg,
                 const float* __restrict__ bias, float* __restrict__ Cg,
                 int Mrows, int Ncols, int Kdim,
                 long sA, long sB, long sC, float alpha, int accum)
{
    const int BM = 128, BN = 128, BK = 16;
    __shared__ float As[BK][BM];
    __shared__ float Bs[BK][BN];

    A  += (long)blockIdx.z * sA;
    Bg += (long)blockIdx.z * sB;
    Cg += (long)blockIdx.z * sC;

    const int i0 = blockIdx.y * BM;
    const int j0 = blockIdx.x * BN;
    const int tid = threadIdx.x;
    const int tx = tid & 15, ty = tid >> 4;

    float acc[8][8];
#pragma unroll
    for (int i = 0; i < 8; i++)
#pragma unroll
        for (int j = 0; j < 8; j++) acc[i][j] = 0.f;

    for (int k0 = 0; k0 < Kdim; k0 += BK) {
        // load A tile (transposed into As[k][i])
#pragma unroll
        for (int q = 0; q < 2; q++) {
            int f = tid + q * 256;          // 0..511 float4 slots
            int row = f >> 2, kc = f & 3;
            float4 v = *(const float4*)&A[(long)(i0 + row) * Kdim + k0 + kc * 4];
            As[kc * 4 + 0][row] = v.x;
            As[kc * 4 + 1][row] = v.y;
            As[kc * 4 + 2][row] = v.z;
            As[kc * 4 + 3][row] = v.w;
        }
        if (TRANS_B) {
#pragma unroll
            for (int q = 0; q < 2; q++) {
                int f = tid + q * 256;
                int row = f >> 2, kc = f & 3;   // row = j index
                float4 v = *(const float4*)&Bg[(long)(j0 + row) * Kdim + k0 + kc * 4];
                Bs[kc * 4 + 0][row] = v.x;
                Bs[kc * 4 + 1][row] = v.y;
                Bs[kc * 4 + 2][row] = v.z;
                Bs[kc * 4 + 3][row] = v.w;
            }
        } else {
#pragma unroll
            for (int q = 0; q < 2; q++) {
                int f = tid + q * 256;
                int kr = f >> 5, jc = f & 31;
                float4 v = *(const float4*)&Bg[(long)(k0 + kr) * Ncols + j0 + jc * 4];
                *(float4*)&Bs[kr][jc * 4] = v;
            }
        }
        __syncthreads();

#pragma unroll
        for (int k = 0; k < BK; k++) {
            float ar[8], br[8];
            *(float4*)&ar[0] = *(const float4*)&As[k][ty * 8];
            *(float4*)&ar[4] = *(const float4*)&As[k][ty * 8 + 4];
            *(float4*)&br[0] = *(const float4*)&Bs[k][tx * 8];
            *(float4*)&br[4] = *(const float4*)&Bs[k][tx * 8 + 4];
#pragma unroll
            for (int ii = 0; ii < 8; ii++)
#pragma unroll
                for (int jj = 0; jj < 8; jj++)
                    acc[ii][jj] += ar[ii] * br[jj];
        }
        __syncthreads();
    }

#pragma unroll
    for (int ii = 0; ii < 8; ii++) {
        long r = i0 + ty * 8 + ii;
#pragma unroll
        for (int jj = 0; jj < 8; jj++) {
            int jc = j0 + tx * 8 + jj;
            float v = acc[ii][jj] * alpha;
            if (bias) v += bias[jc];
            if (accum) v += Cg[r * Ncols + jc];
            Cg[r * Ncols + jc] = v;
        }
    }
}

// ---------------- fast deterministic CSR build ----------------------------
// Stage 0: zero counters
__global__ void zero_cnt_kernel(int* ncnt, int* ecnt)
{
    int i = blockIdx.x * blockDim.x + threadIdx.x;
    if (i < 3 * Nn) ncnt[i] = 0;
    if (i < 3 * Mm) ecnt[i] = 0;
}

// Stage 1: count members per segment (integer atomics -> deterministic)
// grid.y = modality. idx_m = hidx[m] (+Cc for edges).
__global__ void csr_count_kernel(const int* __restrict__ i0, const int* __restrict__ i1,
                                 const int* __restrict__ i2, int cnt_stride, int edge_off,
                                 int* __restrict__ cnt)
{
    const int* idx = (blockIdx.y == 0) ? i0 : (blockIdx.y == 1) ? i1 : i2;
    int c = blockIdx.x * blockDim.x + threadIdx.x;
    atomicAdd(&cnt[blockIdx.y * cnt_stride + idx[edge_off + c]], 1);
}

// Stage 2: exclusive scan over nseg counters (one block per modality)
__global__ void csr_scan_kernel(const int* __restrict__ cnt, int* __restrict__ off, int nseg)
{
    __shared__ int buf[1024];
    int tid = threadIdx.x;
    int v = (tid < nseg) ? cnt[blockIdx.x * nseg + tid] : 0;
    buf[tid] = v;
    __syncthreads();
    for (int o = 1; o < nseg; o <<= 1) {
        int t = (tid >= o) ? buf[tid - o] : 0;
        __syncthreads();
        buf[tid] += t;
        __syncthreads();
    }
    if (tid < nseg) off[blockIdx.x * nseg + tid] = buf[tid] - v;
}

// Stage 3: fill lists in ascending-c order (warp per segment, ballot ranking)
// Deterministic: each segment's member list is sorted by c.
__global__ void csr_fill_kernel(const int* __restrict__ i0, const int* __restrict__ i1,
                                const int* __restrict__ i2, int nseg, int edge_off,
                                const int* __restrict__ off, int* __restrict__ list)
{
    __shared__ int sidx[Cc];
    const int* idx = (blockIdx.y == 0) ? i0 : (blockIdx.y == 1) ? i1 : i2;
    int tid = threadIdx.x;
    for (int i = tid; i < Cc; i += blockDim.x) sidx[i] = idx[edge_off + i];
    __syncthreads();

    int w = tid >> 5, lane = tid & 31;
    int s = blockIdx.x * 8 + w;              // 8 warps -> 8 segments per block
    if (s >= nseg) return;
    int p = off[blockIdx.y * nseg + s];
    int* lst = list + blockIdx.y * Cc;
    for (int c0 = 0; c0 < Cc; c0 += 32) {
        int c = c0 + lane;
        bool m = (sidx[c] == s);
        unsigned bal = __ballot_sync(0xffffffffu, m);
        if (m) lst[p + __popc(bal & ((1u << lane) - 1u))] = c;
        p += __popc(bal);
    }
}

// ---------------- edge_sums[e,b,:] = sum_{c in edge e} xp[b, node[c], :] --
__global__ void edge_sum_kernel(const float* __restrict__ xp, const int* __restrict__ hidx,
                                const int* __restrict__ ecnt, const int* __restrict__ eoff,
                                const int* __restrict__ elist, float* __restrict__ es)
{
    int e = blockIdx.x, b = blockIdx.y, d = threadIdx.x;
    int cnt = ecnt[e], off = eoff[e];
    float s = 0.f;
    for (int i = 0; i < cnt; i++) {
        int c = elist[off + i];
        int node = hidx[c];
        s += xp[((long)b * Nn + node) * Dd + d];
    }
    es[((long)e * Bdim + b) * Dd + d] = s;
}

// ---------------- attention logits e[c,b] (leaky relu applied) -----------
__global__ void logits_kernel(const float* __restrict__ xp, const float* __restrict__ es,
                              const int* __restrict__ hidx, const float* __restrict__ att,
                              float* __restrict__ e_out)
{
    int c = blockIdx.x;
    int node = hidx[c], edge = hidx[Cc + c];
    __shared__ float satt[2 * Dd];
    int tid = threadIdx.x;
    satt[tid] = att[tid];
    satt[tid + Dd] = att[tid + Dd];
    __syncthreads();

    int w = tid >> 5, lane = tid & 31;
    for (int bb = w; bb < Bdim; bb += 8) {
        float s = 0.f;
#pragma unroll
        for (int i = 0; i < Dd / 32; i++) {
            int d = lane + 32 * i;
            s += xp[((long)bb * Nn + node) * Dd + d] * satt[d]
               + es[((long)edge * Bdim + bb) * Dd + d] * satt[Dd + d];
        }
#pragma unroll
        for (int o = 16; o; o >>= 1) s += __shfl_xor_sync(0xffffffffu, s, o);
        if (lane == 0) {
            float v = (s >= 0.f) ? s : NEG_SLOPE * s;
            e_out[c * Bdim + bb] = v;
        }
    }
}

// ---------------- grouped softmax by node (in place e -> alpha) ----------
__global__ void node_softmax(float* __restrict__ e, const int* __restrict__ ncnt,
                             const int* __restrict__ noff, const int* __restrict__ nlist)
{
    int n = blockIdx.x, b = threadIdx.x;
    if (b >= Bdim) return;
    int cnt = ncnt[n];
    if (!cnt) return;
    int off = noff[n];
    float mx = -1e30f;
    for (int i = 0; i < cnt; i++) {
        int c = nlist[off + i];
        mx = fmaxf(mx, e[c * Bdim + b]);
    }
    float sum = 0.f;
    for (int i = 0; i < cnt; i++) {
        int c = nlist[off + i];
        float v = expf(e[c * Bdim + b] - mx);
        e[c * Bdim + b] = v;
        sum += v;
    }
    float inv = 1.f / (sum + 1e-16f);
    for (int i = 0; i < cnt; i++) {
        int c = nlist[off + i];
        e[c * Bdim + b] *= inv;
    }
}

// ---------------- x_edge[e,b,:] = (1/|e|) sum alpha[c,b]*xp[b,node[c],:] --
__global__ void xedge_kernel(const float* __restrict__ xp, const float* __restrict__ alpha,
                             const int* __restrict__ hidx,
                             const int* __restrict__ ecnt, const int* __restrict__ eoff,
                             const int* __restrict__ elist, float* __restrict__ xe)
{
    int e = blockIdx.x, b = blockIdx.y, d = threadIdx.x;
    int cnt = ecnt[e];
    float s = 0.f;
    if (cnt) {
        int off = eoff[e];
        for (int i = 0; i < cnt; i++) {
            int c = elist[off + i];
            int node = hidx[c];
            s += alpha[c * Bdim + b] * xp[((long)b * Nn + node) * Dd + d];
        }
        s /= (float)cnt;
    }
    xe[((long)e * Bdim + b) * Dd + d] = s;
}

// ---------------- h[b,n,:] = (1/|n|) sum alpha[c,b]*x_edge[edge[c],b,:] ---
__global__ void xnode_kernel(const float* __restrict__ xe, const float* __restrict__ alpha,
                             const int* __restrict__ hidx,
                             const int* __restrict__ ncnt, const int* __restrict__ noff,
                             const int* __restrict__ nlist, float* __restrict__ h)
{
    int n = blockIdx.x, b = blockIdx.y, d = threadIdx.x;
    int cnt = ncnt[n];
    float s = 0.f;
    if (cnt) {
        int off = noff[n];
        for (int i = 0; i < cnt; i++) {
            int c = nlist[off + i];
            int eidx = hidx[Cc + c];
            s += alpha[c * Bdim + b] * xe[((long)eidx * Bdim + b) * Dd + d];
        }
        s /= (float)cnt;
    }
    h[((long)b * Nn + n) * Dd + d] = s;
}

// ---------------- row softmax over 1024-wide rows ------------------------
__global__ void softmax_rows(float* __restrict__ S)
{
    long row = blockIdx.x;
    float* p = S + row * 1024;
    int tid = threadIdx.x;
    float v[4];
    float mx = -1e30f;
#pragma unroll
    for (int i = 0; i < 4; i++) {
        v[i] = p[tid + 256 * i];
        mx = fmaxf(mx, v[i]);
    }
    __shared__ float red[256];
    red[tid] = mx;
    __syncthreads();
    for (int o = 128; o; o >>= 1) {
        if (tid < o) red[tid] = fmaxf(red[tid], red[tid + o]);
        __syncthreads();
    }
    mx = red[0];
    __syncthreads();
    float s = 0.f;
#pragma unroll
    for (int i = 0; i < 4; i++) {
        v[i] = expf(v[i] - mx);
        s += v[i];
    }
    red[tid] = s;
    __syncthreads();
    for (int o = 128; o; o >>= 1) {
        if (tid < o) red[tid] += red[tid + o];
        __syncthreads();
    }
    float inv = 1.f / red[0];
#pragma unroll
    for (int i = 0; i < 4; i++) p[tid + 256 * i] = v[i] * inv;
}

// ---------------- relu -----------------------------------------------------
__global__ void relu_kernel(float* __restrict__ p, long n)
{
    long i = (long)blockIdx.x * blockDim.x + threadIdx.x;
    long stride = (long)gridDim.x * blockDim.x;
    for (; i < n; i += stride) p[i] = fmaxf(p[i], 0.f);
}

// ---------------- launcher -------------------------------------------------
extern "C" void kernel_launch(void* const* d_in, const int* in_sizes, int n_in,
                              void* d_out, int out_size)
{
    const float* x[3]    = {(const float*)d_in[0], (const float*)d_in[1], (const float*)d_in[2]};
    const int*   hidx[3] = {(const int*)d_in[3], (const int*)d_in[4], (const int*)d_in[5]};
    const float* W_hg = (const float*)d_in[6];
    const float* att  = (const float*)d_in[7];
    const float* WQ = (const float*)d_in[8];
    const float* bQ = (const float*)d_in[9];
    const float* WK = (const float*)d_in[10];
    const float* bK = (const float*)d_in[11];
    const float* WV = (const float*)d_in[12];
    const float* bV = (const float*)d_in[13];
    const float* WO = (const float*)d_in[14];
    const float* bO = (const float*)d_in[15];
    float* out = (float*)d_out;

    float *xp, *h, *Q, *Kb, *Vb, *S, *es, *xe, *ealpha;
    int *ncnt, *noff, *nlist, *ecnt, *eoff, *elist;
    cudaGetSymbolAddress((void**)&xp, g_xp);
    cudaGetSymbolAddress((void**)&h,  g_h);
    cudaGetSymbolAddress((void**)&Q,  g_Q);
    cudaGetSymbolAddress((void**)&Kb, g_Kb);
    cudaGetSymbolAddress((void**)&Vb, g_Vb);
    cudaGetSymbolAddress((void**)&S,  g_S);
    cudaGetSymbolAddress((void**)&es, g_es);
    cudaGetSymbolAddress((void**)&xe, g_xe);
    cudaGetSymbolAddress((void**)&ealpha, g_e);
    cudaGetSymbolAddress((void**)&ncnt, g_ncnt);
    cudaGetSymbolAddress((void**)&noff, g_noff);
    cudaGetSymbolAddress((void**)&nlist, g_nlist);
    cudaGetSymbolAddress((void**)&ecnt, g_ecnt);
    cudaGetSymbolAddress((void**)&eoff, g_eoff);
    cudaGetSymbolAddress((void**)&elist, g_elist);

    const long ND = (long)Nn * Dd;       // per-batch stride within a modality
    const long NN2 = (long)Nn * Nn;

    // 1) xp = x @ W_hg  (per modality: [16384,256] @ [256,256])
    for (int m = 0; m < 3; m++)
        gemm_kernel<false><<<dim3(2, 128, 1), 256>>>(
            x[m], W_hg, nullptr, xp + (long)m * BND,
            Bdim * Nn, Dd, Dd, 0, 0, 0, 1.f, 0);

    // 2) CSR build (parallel, deterministic: lists sorted by c)
    zero_cnt_kernel<<<4, 1024>>>(ncnt, ecnt);
    csr_count_kernel<<<dim3(Cc / 256, 3), 256>>>(hidx[0], hidx[1], hidx[2], Nn, 0,  ncnt);
    csr_count_kernel<<<dim3(Cc / 256, 3), 256>>>(hidx[0], hidx[1], hidx[2], Mm, Cc, ecnt);
    csr_scan_kernel<<<3, 1024>>>(ncnt, noff, Nn);
    csr_scan_kernel<<<3, 1024>>>(ecnt, eoff, Mm);
    csr_fill_kernel<<<dim3(Nn / 8, 3), 256>>>(hidx[0], hidx[1], hidx[2], Nn, 0,  noff, nlist);
    csr_fill_kernel<<<dim3(Mm / 8, 3), 256>>>(hidx[0], hidx[1], hidx[2], Mm, Cc, eoff, elist);

    // 3) edge_sums
    for (int m = 0; m < 3; m++)
        edge_sum_kernel<<<dim3(Mm, Bdim), Dd>>>(
            xp + (long)m * BND, hidx[m],
            ecnt + m * Mm, eoff + m * Mm, elist + m * Cc,
            es + (long)m * Mm * Bdim * Dd);

    // 4) logits + leaky relu
    for (int m = 0; m < 3; m++)
        logits_kernel<<<Cc, 256>>>(
            xp + (long)m * BND, es + (long)m * Mm * Bdim * Dd,
            hidx[m], att, ealpha + (long)m * Cc * Bdim);

    // 5) grouped softmax (e -> alpha in place)
    for (int m = 0; m < 3; m++)
        node_softmax<<<Nn, 32>>>(
            ealpha + (long)m * Cc * Bdim,
            ncnt + m * Nn, noff + m * Nn, nlist + m * Cc);

    // 6) x_edge
    for (int m = 0; m < 3; m++)
        xedge_kernel<<<dim3(Mm, Bdim), Dd>>>(
            xp + (long)m * BND, ealpha + (long)m * Cc * Bdim, hidx[m],
            ecnt + m * Mm, eoff + m * Mm, elist + m * Cc,
            xe + (long)m * Mm * Bdim * Dd);

    // 7) x_node -> h (transposed to [B,N,D])
    for (int m = 0; m < 3; m++)
        xnode_kernel<<<dim3(Nn, Bdim), Dd>>>(
            xe + (long)m * Mm * Bdim * Dd, ealpha + (long)m * Cc * Bdim, hidx[m],
            ncnt + m * Nn, noff + m * Nn, nlist + m * Cc,
            h + (long)m * BND);

    // 8) projections over all modalities at once ([49152,256] @ [256,256])
    gemm_kernel<false><<<dim3(2, 384, 1), 256>>>(h, WQ, bQ, Q,  3 * Bdim * Nn, Dd, Dd, 0, 0, 0, 1.f, 0);
    gemm_kernel<false><<<dim3(2, 384, 1), 256>>>(h, WK, bK, Kb, 3 * Bdim * Nn, Dd, Dd, 0, 0, 0, 1.f, 0);
    gemm_kernel<false><<<dim3(2, 384, 1), 256>>>(h, WV, bV, Vb, 3 * Bdim * Nn, Dd, Dd, 0, 0, 0, 1.f, 0);
    // base: out = h @ WO + bO  (msg accumulated into it below)
    gemm_kernel<false><<<dim3(2, 384, 1), 256>>>(h, WO, bO, out, 3 * Bdim * Nn, Dd, Dd, 0, 0, 0, 1.f, 0);

    // 9) cross-modal attention, 6 (m,n) pairs
    const float scale = 0.0625f;   // 1/sqrt(256)
    for (int m = 0; m < 3; m++) {
        for (int n = 0; n < 3; n++) {
            if (n == m) continue;
            // S = scale * Q_m @ K_n^T  (batched over B)
            gemm_kernel<true><<<dim3(8, 8, Bdim), 256>>>(
                Q + (long)m * BND, Kb + (long)n * BND, nullptr, S,
                Nn, Nn, Dd, ND, ND, NN2, scale, 0);
            softmax_rows<<<Bdim * Nn, 256>>>(S);
            // out_m += S @ V_n
            gemm_kernel<false><<<dim3(2, 8, Bdim), 256>>>(
                S, Vb + (long)n * BND, nullptr, out + (long)m * BND,
                Nn, Dd, Nn, NN2, ND, ND, 1.f, 1);
        }
    }

    // 10) final relu
    relu_kernel<<<4096, 256>>>(out, 3L * BND);
}

// round 4
// speedup vs baseline: 3.2589x; 2.4375x over previous
#include <cuda_runtime.h>
#include <stdint.h>
#include <math.h>

// Problem constants
#define Bdim 16
#define Nn   1024
#define Dd   256
#define Mm   128
#define Cc   8192
#define NEG_SLOPE 0.2f

static const int BND = Bdim * Nn * Dd;          // 4,194,304

// ---------------- scratch (device globals; no allocation) ----------------
__device__ float g_xp[3 * Bdim * Nn * Dd];      // projected inputs
__device__ float g_h [3 * Bdim * Nn * Dd];      // hypergraph outputs (tf32-rounded)
__device__ float g_Q [3 * Bdim * Nn * Dd];      // tf32-rounded
__device__ float g_Kb[3 * Bdim * Nn * Dd];      // tf32-rounded
__device__ float g_Vb[3 * Bdim * Nn * Dd];
__device__ float g_VT[3 * Bdim * Dd * Nn];      // V transposed, tf32-rounded
__device__ float g_WT[5 * Dd * Dd];             // W_hg,WQ,WK,WV,WO transposed+rounded
__device__ float g_S [Bdim * Nn * Nn];          // attention probs (rounded by softmax)
__device__ float g_es[3 * Mm * Bdim * Dd];      // edge_sums
__device__ float g_xe[3 * Mm * Bdim * Dd];      // x_edge
__device__ float g_e [3 * Cc * Bdim];           // logits -> alpha (in place)
__device__ int   g_ncnt[3 * Nn], g_noff[3 * Nn], g_nlist[3 * Cc];
__device__ int   g_ecnt[3 * Mm], g_eoff[3 * Mm], g_elist[3 * Cc];

// ---------------- helpers -------------------------------------------------
__device__ __forceinline__ uint32_t smem_u32(const void* p) {
    uint32_t a;
    asm("{ .reg .u64 t; cvta.to.shared.u64 t, %1; cvt.u32.u64 %0, t; }"
        : "=r"(a) : "l"(p));
    return a;
}
__device__ __forceinline__ uint32_t swz64(uint32_t off) {
    return off ^ ((off >> 3) & 0x30);
}
__device__ __forceinline__ uint32_t rna_u(float x) {
    uint32_t r;
    asm("cvt.rna.tf32.f32 %0, %1;" : "=r"(r) : "f"(x));
    return r;
}
__device__ __forceinline__ float rna_f(float x) { return __uint_as_float(rna_u(x)); }

__device__ __forceinline__ void ldsm4(uint32_t* r, uint32_t addr) {
    asm volatile("ldmatrix.sync.aligned.m8n8.x4.shared.b16 {%0,%1,%2,%3}, [%4];"
        : "=r"(r[0]), "=r"(r[1]), "=r"(r[2]), "=r"(r[3]) : "r"(addr));
}
__device__ __forceinline__ void mma8(float* c, const uint32_t* a, const uint32_t* b) {
    asm volatile(
        "mma.sync.aligned.m16n8k8.row.col.f32.tf32.tf32.f32 "
        "{%0,%1,%2,%3}, {%4,%5,%6,%7}, {%8,%9}, {%0,%1,%2,%3};"
        : "+f"(c[0]), "+f"(c[1]), "+f"(c[2]), "+f"(c[3])
        : "r"(a[0]), "r"(a[1]), "r"(a[2]), "r"(a[3]), "r"(b[0]), "r"(b[1]));
}

// ---------------- tf32 mma GEMM ------------------------------------------
// C[M,N] = alpha * A[M,K] @ B^T (+bias) (+C).  A row-major [M,K], B row-major [N,K].
// Requires M%128==0, N%128==0, K%16==0.
// cvtA: round A to tf32 (rna) during load (use when A is not pre-rounded).
// rndC: round output to tf32 before store (for outputs reused as MMA operands).
__global__ __launch_bounds__(256)
void gemm_mma(const float* __restrict__ A, const float* __restrict__ Bg,
              const float* __restrict__ bias, float* __restrict__ Cg,
              int Mrows, int Ncols, int Kdim,
              long sA, long sB, long sC, float alpha,
              int accum, int cvtA, int rndC)
{
    __shared__ __align__(16) float smA[2][128 * 16];   // K-major, 64B rows, swz64
    __shared__ __align__(16) float smB[2][128 * 16];   // [n][k] K-major

    const int tid = threadIdx.x, lane = tid & 31, wid = tid >> 5;
    const int wm = (wid & 1) * 64, wn = (wid >> 1) * 32;

    A  += (long)blockIdx.z * sA;
    Bg += (long)blockIdx.z * sB;
    Cg += (long)blockIdx.z * sC;
    const int i0 = blockIdx.y * 128;
    const int j0 = blockIdx.x * 128;

    float acc[4][4][4];
#pragma unroll
    for (int i = 0; i < 4; i++)
#pragma unroll
        for (int j = 0; j < 4; j++)
#pragma unroll
            for (int c = 0; c < 4; c++) acc[i][j][c] = 0.f;

    const uint32_t baseA = smem_u32(smA), baseB = smem_u32(smB);
    // per-lane ldmatrix offsets (bytes, before swizzle)
    const uint32_t aoff = (uint32_t)((wm + (lane & 7) + (lane & 8)) * 64
                                     + ((lane >> 4) & 1) * 16);
    const uint32_t boff = (uint32_t)((wn + (lane & 7) + ((lane >> 4) & 1) * 8) * 64
                                     + ((lane >> 3) & 1) * 16);

    // loader slots: f = tid + q*256 -> row f>>2 (0..127), k-quad f&3
    const int lr = tid >> 2, lk = (tid & 3) * 4;

    float4 stA[2], stB[2];
    const int nkt = Kdim >> 4;

    // preload tile 0
#pragma unroll
    for (int q = 0; q < 2; q++) {
        int r = lr + q * 64;
        stA[q] = *(const float4*)&A[(long)(i0 + r) * Kdim + lk];
        stB[q] = *(const float4*)&Bg[(long)(j0 + r) * Kdim + lk];
    }
    {
#pragma unroll
        for (int q = 0; q < 2; q++) {
            int r = lr + q * 64;
            uint4 va, vb;
            if (cvtA) {
                va.x = rna_u(stA[q].x); va.y = rna_u(stA[q].y);
                va.z = rna_u(stA[q].z); va.w = rna_u(stA[q].w);
            } else va = *(uint4*)&stA[q];
            vb = *(uint4*)&stB[q];
            *(uint4*)((char*)smA[0] + swz64(r * 64 + (lk << 2))) = va;
            *(uint4*)((char*)smB[0] + swz64(r * 64 + (lk << 2))) = vb;
        }
    }
    __syncthreads();

    for (int kt = 0; kt < nkt; kt++) {
        // issue global loads for next tile (latency overlapped with compute)
        if (kt + 1 < nkt) {
            int k0 = (kt + 1) << 4;
#pragma unroll
            for (int q = 0; q < 2; q++) {
                int r = lr + q * 64;
                stA[q] = *(const float4*)&A[(long)(i0 + r) * Kdim + k0 + lk];
                stB[q] = *(const float4*)&Bg[(long)(j0 + r) * Kdim + k0 + lk];
            }
        }

        const int buf = kt & 1;
        const uint32_t sa = baseA + buf * 8192;
        const uint32_t sb = baseB + buf * 8192;
#pragma unroll
        for (int s = 0; s < 2; s++) {
            uint32_t af[4][4], bf[4][2];
#pragma unroll
            for (int mt = 0; mt < 4; mt++)
                ldsm4(af[mt], sa + swz64(aoff + mt * 1024 + s * 32));
#pragma unroll
            for (int p = 0; p < 2; p++) {
                uint32_t r[4];
                ldsm4(r, sb + swz64(boff + p * 1024 + s * 32));
                bf[2 * p][0] = r[0]; bf[2 * p][1] = r[1];
                bf[2 * p + 1][0] = r[2]; bf[2 * p + 1][1] = r[3];
            }
#pragma unroll
            for (int mt = 0; mt < 4; mt++)
#pragma unroll
                for (int nt = 0; nt < 4; nt++)
                    mma8(acc[mt][nt], af[mt], bf[nt]);
        }
        __syncthreads();

        if (kt + 1 < nkt) {
            const int nbuf = (kt + 1) & 1;
#pragma unroll
            for (int q = 0; q < 2; q++) {
                int r = lr + q * 64;
                uint4 va, vb;
                if (cvtA) {
                    va.x = rna_u(stA[q].x); va.y = rna_u(stA[q].y);
                    va.z = rna_u(stA[q].z); va.w = rna_u(stA[q].w);
                } else va = *(uint4*)&stA[q];
                vb = *(uint4*)&stB[q];
                *(uint4*)((char*)smA[nbuf] + swz64(r * 64 + (lk << 2))) = va;
                *(uint4*)((char*)smB[nbuf] + swz64(r * 64 + (lk << 2))) = vb;
            }
            __syncthreads();
        }
    }

    // epilogue
#pragma unroll
    for (int mt = 0; mt < 4; mt++) {
        int row = i0 + wm + mt * 16 + (lane >> 2);
#pragma unroll
        for (int nt = 0; nt < 4; nt++) {
            int col = j0 + wn + nt * 8 + (lane & 3) * 2;
            float bb0 = 0.f, bb1 = 0.f;
            if (bias) { bb0 = bias[col]; bb1 = bias[col + 1]; }
            long p0 = (long)row * Ncols + col;
            long p1 = (long)(row + 8) * Ncols + col;
            float v0 = acc[mt][nt][0] * alpha + bb0;
            float v1 = acc[mt][nt][1] * alpha + bb1;
            float v2 = acc[mt][nt][2] * alpha + bb0;
            float v3 = acc[mt][nt][3] * alpha + bb1;
            if (accum) {
                float2 c0 = *(float2*)&Cg[p0];
                float2 c1 = *(float2*)&Cg[p1];
                v0 += c0.x; v1 += c0.y; v2 += c1.x; v3 += c1.y;
            }
            if (rndC) { v0 = rna_f(v0); v1 = rna_f(v1); v2 = rna_f(v2); v3 = rna_f(v3); }
            *(float2*)&Cg[p0] = make_float2(v0, v1);
            *(float2*)&Cg[p1] = make_float2(v2, v3);
        }
    }
}

// ---------------- transpose (dst[C][R] = src[R][C]), optional tf32 round --
__global__ void transpose_kernel(const float* __restrict__ src, float* __restrict__ dst,
                                 int R, int C, long sS, long sD, int rnd)
{
    __shared__ float t[32][33];
    src += (long)blockIdx.z * sS;
    dst += (long)blockIdx.z * sD;
    int c = blockIdx.x * 32 + threadIdx.x;
    int r0 = blockIdx.y * 32;
    for (int j = threadIdx.y; j < 32; j += 8)
        t[j][threadIdx.x] = src[(long)(r0 + j) * C + c];
    __syncthreads();
    int rr = blockIdx.y * 32 + threadIdx.x;
    int cc0 = blockIdx.x * 32;
    for (int j = threadIdx.y; j < 32; j += 8) {
        float v = t[threadIdx.x][j];
        if (rnd) v = rna_f(v);
        dst[(long)(cc0 + j) * R + rr] = v;
    }
}

// ---------------- fast deterministic CSR build ----------------------------
__global__ void zero_cnt_kernel(int* ncnt, int* ecnt)
{
    int i = blockIdx.x * blockDim.x + threadIdx.x;
    if (i < 3 * Nn) ncnt[i] = 0;
    if (i < 3 * Mm) ecnt[i] = 0;
}

__global__ void csr_count_kernel(const int* __restrict__ i0, const int* __restrict__ i1,
                                 const int* __restrict__ i2, int cnt_stride, int edge_off,
                                 int* __restrict__ cnt)
{
    const int* idx = (blockIdx.y == 0) ? i0 : (blockIdx.y == 1) ? i1 : i2;
    int c = blockIdx.x * blockDim.x + threadIdx.x;
    atomicAdd(&cnt[blockIdx.y * cnt_stride + idx[edge_off + c]], 1);
}

__global__ void csr_scan_kernel(const int* __restrict__ cnt, int* __restrict__ off, int nseg)
{
    __shared__ int buf[1024];
    int tid = threadIdx.x;
    int v = (tid < nseg) ? cnt[blockIdx.x * nseg + tid] : 0;
    buf[tid] = v;
    __syncthreads();
    for (int o = 1; o < nseg; o <<= 1) {
        int t = (tid >= o) ? buf[tid - o] : 0;
        __syncthreads();
        buf[tid] += t;
        __syncthreads();
    }
    if (tid < nseg) off[blockIdx.x * nseg + tid] = buf[tid] - v;
}

__global__ void csr_fill_kernel(const int* __restrict__ i0, const int* __restrict__ i1,
                                const int* __restrict__ i2, int nseg, int edge_off,
                                const int* __restrict__ off, int* __restrict__ list)
{
    __shared__ int sidx[Cc];
    const int* idx = (blockIdx.y == 0) ? i0 : (blockIdx.y == 1) ? i1 : i2;
    int tid = threadIdx.x;
    for (int i = tid; i < Cc; i += blockDim.x) sidx[i] = idx[edge_off + i];
    __syncthreads();

    int w = tid >> 5, lane = tid & 31;
    int s = blockIdx.x * 8 + w;
    if (s >= nseg) return;
    int p = off[blockIdx.y * nseg + s];
    int* lst = list + blockIdx.y * Cc;
    for (int c0 = 0; c0 < Cc; c0 += 32) {
        int c = c0 + lane;
        bool m = (sidx[c] == s);
        unsigned bal = __ballot_sync(0xffffffffu, m);
        if (m) lst[p + __popc(bal & ((1u << lane) - 1u))] = c;
        p += __popc(bal);
    }
}

// ---------------- edge_sums[e,b,:] = sum_{c in edge e} xp[b, node[c], :] --
__global__ void edge_sum_kernel(const float* __restrict__ xp, const int* __restrict__ hidx,
                                const int* __restrict__ ecnt, const int* __restrict__ eoff,
                                const int* __restrict__ elist, float* __restrict__ es)
{
    int e = blockIdx.x, b = blockIdx.y, d = threadIdx.x;
    int cnt = ecnt[e], off = eoff[e];
    float s = 0.f;
    for (int i = 0; i < cnt; i++) {
        int c = elist[off + i];
        int node = hidx[c];
        s += xp[((long)b * Nn + node) * Dd + d];
    }
    es[((long)e * Bdim + b) * Dd + d] = s;
}

// ---------------- attention logits e[c,b] (leaky relu applied) -----------
__global__ void logits_kernel(const float* __restrict__ xp, const float* __restrict__ es,
                              const int* __restrict__ hidx, const float* __restrict__ att,
                              float* __restrict__ e_out)
{
    int c = blockIdx.x;
    int node = hidx[c], edge = hidx[Cc + c];
    __shared__ float satt[2 * Dd];
    int tid = threadIdx.x;
    satt[tid] = att[tid];
    satt[tid + Dd] = att[tid + Dd];
    __syncthreads();

    int w = tid >> 5, lane = tid & 31;
    for (int bb = w; bb < Bdim; bb += 8) {
        float s = 0.f;
#pragma unroll
        for (int i = 0; i < Dd / 32; i++) {
            int d = lane + 32 * i;
            s += xp[((long)bb * Nn + node) * Dd + d] * satt[d]
               + es[((long)edge * Bdim + bb) * Dd + d] * satt[Dd + d];
        }
#pragma unroll
        for (int o = 16; o; o >>= 1) s += __shfl_xor_sync(0xffffffffu, s, o);
        if (lane == 0) {
            float v = (s >= 0.f) ? s : NEG_SLOPE * s;
            e_out[c * Bdim + bb] = v;
        }
    }
}

// ---------------- grouped softmax by node (in place e -> alpha) ----------
__global__ void node_softmax(float* __restrict__ e, const int* __restrict__ ncnt,
                             const int* __restrict__ noff, const int* __restrict__ nlist)
{
    int n = blockIdx.x, b = threadIdx.x;
    if (b >= Bdim) return;
    int cnt = ncnt[n];
    if (!cnt) return;
    int off = noff[n];
    float mx = -1e30f;
    for (int i = 0; i < cnt; i++) {
        int c = nlist[off + i];
        mx = fmaxf(mx, e[c * Bdim + b]);
    }
    float sum = 0.f;
    for (int i = 0; i < cnt; i++) {
        int c = nlist[off + i];
        float v = expf(e[c * Bdim + b] - mx);
        e[c * Bdim + b] = v;
        sum += v;
    }
    float inv = 1.f / (sum + 1e-16f);
    for (int i = 0; i < cnt; i++) {
        int c = nlist[off + i];
        e[c * Bdim + b] *= inv;
    }
}

// ---------------- x_edge[e,b,:] = (1/|e|) sum alpha[c,b]*xp[b,node[c],:] --
__global__ void xedge_kernel(const float* __restrict__ xp, const float* __restrict__ alpha,
                             const int* __restrict__ hidx,
                             const int* __restrict__ ecnt, const int* __restrict__ eoff,
                             const int* __restrict__ elist, float* __restrict__ xe)
{
    int e = blockIdx.x, b = blockIdx.y, d = threadIdx.x;
    int cnt = ecnt[e];
    float s = 0.f;
    if (cnt) {
        int off = eoff[e];
        for (int i = 0; i < cnt; i++) {
            int c = elist[off + i];
            int node = hidx[c];
            s += alpha[c * Bdim + b] * xp[((long)b * Nn + node) * Dd + d];
        }
        s /= (float)cnt;
    }
    xe[((long)e * Bdim + b) * Dd + d] = s;
}

// ---------------- h[b,n,:] = (1/|n|) sum alpha[c,b]*x_edge[edge[c],b,:] ---
// Output rounded to tf32 (h is a GEMM A-operand downstream).
__global__ void xnode_kernel(const float* __restrict__ xe, const float* __restrict__ alpha,
                             const int* __restrict__ hidx,
                             const int* __restrict__ ncnt, const int* __restrict__ noff,
                             const int* __restrict__ nlist, float* __restrict__ h)
{
    int n = blockIdx.x, b = blockIdx.y, d = threadIdx.x;
    int cnt = ncnt[n];
    float s = 0.f;
    if (cnt) {
        int off = noff[n];
        for (int i = 0; i < cnt; i++) {
            int c = nlist[off + i];
            int eidx = hidx[Cc + c];
            s += alpha[c * Bdim + b] * xe[((long)eidx * Bdim + b) * Dd + d];
        }
        s /= (float)cnt;
    }
    h[((long)b * Nn + n) * Dd + d] = rna_f(s);
}

// ---------------- row softmax over 1024-wide rows (tf32-rounded output) ---
__global__ void softmax_rows(float* __restrict__ S)
{
    long row = blockIdx.x;
    float* p = S + row * 1024;
    int tid = threadIdx.x;
    float v[4];
    float mx = -1e30f;
#pragma unroll
    for (int i = 0; i < 4; i++) {
        v[i] = p[tid + 256 * i];
        mx = fmaxf(mx, v[i]);
    }
    __shared__ float red[256];
    red[tid] = mx;
    __syncthreads();
    for (int o = 128; o; o >>= 1) {
        if (tid < o) red[tid] = fmaxf(red[tid], red[tid + o]);
        __syncthreads();
    }
    mx = red[0];
    __syncthreads();
    float s = 0.f;
#pragma unroll
    for (int i = 0; i < 4; i++) {
        v[i] = expf(v[i] - mx);
        s += v[i];
    }
    red[tid] = s;
    __syncthreads();
    for (int o = 128; o; o >>= 1) {
        if (tid < o) red[tid] += red[tid + o];
        __syncthreads();
    }
    float inv = 1.f / red[0];
#pragma unroll
    for (int i = 0; i < 4; i++) p[tid + 256 * i] = rna_f(v[i] * inv);
}

// ---------------- relu -----------------------------------------------------
__global__ void relu_kernel(float* __restrict__ p, long n)
{
    long i = (long)blockIdx.x * blockDim.x + threadIdx.x;
    long stride = (long)gridDim.x * blockDim.x;
    for (; i < n; i += stride) p[i] = fmaxf(p[i], 0.f);
}

// ---------------- launcher -------------------------------------------------
extern "C" void kernel_launch(void* const* d_in, const int* in_sizes, int n_in,
                              void* d_out, int out_size)
{
    const float* x[3]    = {(const float*)d_in[0], (const float*)d_in[1], (const float*)d_in[2]};
    const int*   hidx[3] = {(const int*)d_in[3], (const int*)d_in[4], (const int*)d_in[5]};
    const float* W_hg = (const float*)d_in[6];
    const float* att  = (const float*)d_in[7];
    const float* WQ = (const float*)d_in[8];
    const float* bQ = (const float*)d_in[9];
    const float* WK = (const float*)d_in[10];
    const float* bK = (const float*)d_in[11];
    const float* WV = (const float*)d_in[12];
    const float* bV = (const float*)d_in[13];
    const float* WO = (const float*)d_in[14];
    const float* bO = (const float*)d_in[15];
    float* out = (float*)d_out;

    float *xp, *h, *Q, *Kb, *Vb, *VT, *WT, *S, *es, *xe, *ealpha;
    int *ncnt, *noff, *nlist, *ecnt, *eoff, *elist;
    cudaGetSymbolAddress((void**)&xp, g_xp);
    cudaGetSymbolAddress((void**)&h,  g_h);
    cudaGetSymbolAddress((void**)&Q,  g_Q);
    cudaGetSymbolAddress((void**)&Kb, g_Kb);
    cudaGetSymbolAddress((void**)&Vb, g_Vb);
    cudaGetSymbolAddress((void**)&VT, g_VT);
    cudaGetSymbolAddress((void**)&WT, g_WT);
    cudaGetSymbolAddress((void**)&S,  g_S);
    cudaGetSymbolAddress((void**)&es, g_es);
    cudaGetSymbolAddress((void**)&xe, g_xe);
    cudaGetSymbolAddress((void**)&ealpha, g_e);
    cudaGetSymbolAddress((void**)&ncnt, g_ncnt);
    cudaGetSymbolAddress((void**)&noff, g_noff);
    cudaGetSymbolAddress((void**)&nlist, g_nlist);
    cudaGetSymbolAddress((void**)&ecnt, g_ecnt);
    cudaGetSymbolAddress((void**)&eoff, g_eoff);
    cudaGetSymbolAddress((void**)&elist, g_elist);

    const long ND = (long)Nn * Dd;       // per-batch stride within a modality
    const long NN2 = (long)Nn * Nn;
    const int DD = Dd * Dd;

    // 0) transpose + tf32-round the 5 weight matrices: WT[i] = W_i^T
    {
        dim3 tb(32, 8), tg(8, 8, 1);
        transpose_kernel<<<tg, tb>>>(W_hg, WT + 0 * DD, Dd, Dd, 0, 0, 1);
        transpose_kernel<<<tg, tb>>>(WQ,   WT + 1 * DD, Dd, Dd, 0, 0, 1);
        transpose_kernel<<<tg, tb>>>(WK,   WT + 2 * DD, Dd, Dd, 0, 0, 1);
        transpose_kernel<<<tg, tb>>>(WV,   WT + 3 * DD, Dd, Dd, 0, 0, 1);
        transpose_kernel<<<tg, tb>>>(WO,   WT + 4 * DD, Dd, Dd, 0, 0, 1);
    }

    // 1) xp = x @ W_hg  (A = raw x -> cvtA=1)
    for (int m = 0; m < 3; m++)
        gemm_mma<<<dim3(2, 128, 1), 256>>>(
            x[m], WT + 0 * DD, nullptr, xp + (long)m * BND,
            Bdim * Nn, Dd, Dd, 0, 0, 0, 1.f, 0, 1, 0);

    // 2) CSR build (parallel, deterministic: lists sorted by c)
    zero_cnt_kernel<<<4, 1024>>>(ncnt, ecnt);
    csr_count_kernel<<<dim3(Cc / 256, 3), 256>>>(hidx[0], hidx[1], hidx[2], Nn, 0,  ncnt);
    csr_count_kernel<<<dim3(Cc / 256, 3), 256>>>(hidx[0], hidx[1], hidx[2], Mm, Cc, ecnt);
    csr_scan_kernel<<<3, 1024>>>(ncnt, noff, Nn);
    csr_scan_kernel<<<3, 1024>>>(ecnt, eoff, Mm);
    csr_fill_kernel<<<dim3(Nn / 8, 3), 256>>>(hidx[0], hidx[1], hidx[2], Nn, 0,  noff, nlist);
    csr_fill_kernel<<<dim3(Mm / 8, 3), 256>>>(hidx[0], hidx[1], hidx[2], Mm, Cc, eoff, elist);

    // 3) edge_sums
    for (int m = 0; m < 3; m++)
        edge_sum_kernel<<<dim3(Mm, Bdim), Dd>>>(
            xp + (long)m * BND, hidx[m],
            ecnt + m * Mm, eoff + m * Mm, elist + m * Cc,
            es + (long)m * Mm * Bdim * Dd);

    // 4) logits + leaky relu
    for (int m = 0; m < 3; m++)
        logits_kernel<<<Cc, 256>>>(
            xp + (long)m * BND, es + (long)m * Mm * Bdim * Dd,
            hidx[m], att, ealpha + (long)m * Cc * Bdim);

    // 5) grouped softmax (e -> alpha in place)
    for (int m = 0; m < 3; m++)
        node_softmax<<<Nn, 32>>>(
            ealpha + (long)m * Cc * Bdim,
            ncnt + m * Nn, noff + m * Nn, nlist + m * Cc);

    // 6) x_edge
    for (int m = 0; m < 3; m++)
        xedge_kernel<<<dim3(Mm, Bdim), Dd>>>(
            xp + (long)m * BND, ealpha + (long)m * Cc * Bdim, hidx[m],
            ecnt + m * Mm, eoff + m * Mm, elist + m * Cc,
            xe + (long)m * Mm * Bdim * Dd);

    // 7) x_node -> h (transposed to [B,N,D]; tf32-rounded)
    for (int m = 0; m < 3; m++)
        xnode_kernel<<<dim3(Nn, Bdim), Dd>>>(
            xe + (long)m * Mm * Bdim * Dd, ealpha + (long)m * Cc * Bdim, hidx[m],
            ncnt + m * Nn, noff + m * Nn, nlist + m * Cc,
            h + (long)m * BND);

    // 8) projections ([49152,256] @ [256,256]); Q,K rounded for reuse as operands
    gemm_mma<<<dim3(2, 384, 1), 256>>>(h, WT + 1 * DD, bQ, Q,  3 * Bdim * Nn, Dd, Dd, 0, 0, 0, 1.f, 0, 0, 1);
    gemm_mma<<<dim3(2, 384, 1), 256>>>(h, WT + 2 * DD, bK, Kb, 3 * Bdim * Nn, Dd, Dd, 0, 0, 0, 1.f, 0, 0, 1);
    gemm_mma<<<dim3(2, 384, 1), 256>>>(h, WT + 3 * DD, bV, Vb, 3 * Bdim * Nn, Dd, Dd, 0, 0, 0, 1.f, 0, 0, 0);
    // base: out = h @ WO + bO  (msg accumulated into it below; full fp32 precision)
    gemm_mma<<<dim3(2, 384, 1), 256>>>(h, WT + 4 * DD, bO, out, 3 * Bdim * Nn, Dd, Dd, 0, 0, 0, 1.f, 0, 0, 0);

    // 8b) VT[z][d][n] = V[z][n][d] per (modality,batch) slice, tf32-rounded
    transpose_kernel<<<dim3(Dd / 32, Nn / 32, 48), dim3(32, 8)>>>(
        Vb, VT, Nn, Dd, ND, ND, 1);

    // 9) cross-modal attention, 6 (m,n) pairs
    const float scale = 0.0625f;   // 1/sqrt(256)
    for (int m = 0; m < 3; m++) {
        for (int n = 0; n < 3; n++) {
            if (n == m) continue;
            // S = scale * Q_m @ K_n^T  (batched over B)
            gemm_mma<<<dim3(8, 8, Bdim), 256>>>(
                Q + (long)m * BND, Kb + (long)n * BND, nullptr, S,
                Nn, Nn, Dd, ND, ND, NN2, scale, 0, 0, 0);
            softmax_rows<<<Bdim * Nn, 256>>>(S);
            // out_m += S @ V_n  (B = VT_n, [D rows][N k-cols])
            gemm_mma<<<dim3(2, 8, Bdim), 256>>>(
                S, VT + (long)n * BND, nullptr, out + (long)m * BND,
                Nn, Dd, Nn, NN2, ND, ND, 1.f, 1, 0, 0);
        }
    }

    // 10) final relu
    relu_kernel<<<4096, 256>>>(out, 3L * BND);
}

// round 6
// speedup vs baseline: 3.9043x; 1.1981x over previous
#include <cuda_runtime.h>
#include <stdint.h>
#include <math.h>

// Problem constants
#define Bdim 16
#define Nn   1024
#define Dd   256
#define Mm   128
#define Cc   8192
#define NEG_SLOPE 0.2f

#define BND (Bdim * Nn * Dd)                 // 4,194,304 (per modality)
#define ND  (Nn * Dd)                        // per-batch stride
#define NN2 (Nn * Nn)

// ---------------- scratch (device globals; no allocation) ----------------
__device__ float g_xp[3 * BND];              // projected inputs
__device__ float g_h [3 * BND];              // hypergraph outputs (tf32-rounded)
__device__ float g_Q [3 * BND];              // also used as rounded-x staging
__device__ float g_Kb[3 * BND];
__device__ float g_Vb[3 * BND];
__device__ float g_VT[3 * BND];              // V transposed per (mod,batch), tf32-rounded
__device__ float g_WT[5 * Dd * Dd];          // W_hg,WQ,WK,WV,WO transposed+rounded
__device__ float g_S6[6L * Bdim * Nn * Nn];  // attention scores, all 6 pairs (402MB)
__device__ float g_msg[6L * BND];            // per-pair PV outputs
__device__ float g_es[3 * Mm * Bdim * Dd];
__device__ float g_xe[3 * Mm * Bdim * Dd];
__device__ float g_e [3 * Cc * Bdim];
__device__ int   g_ncnt[3 * Nn], g_noff[3 * Nn], g_nlist[3 * Cc];
__device__ int   g_ecnt[3 * Mm], g_eoff[3 * Mm], g_elist[3 * Cc];

// ---------------- helpers -------------------------------------------------
__device__ __forceinline__ uint32_t smem_u32(const void* p) {
    uint32_t a;
    asm("{ .reg .u64 t; cvta.to.shared.u64 t, %1; cvt.u32.u64 %0, t; }"
        : "=r"(a) : "l"(p));
    return a;
}
__device__ __forceinline__ uint32_t swz64(uint32_t off) {
    return off ^ ((off >> 3) & 0x30);
}
__device__ __forceinline__ uint32_t rna_u(float x) {
    uint32_t r;
    asm("cvt.rna.tf32.f32 %0, %1;" : "=r"(r) : "f"(x));
    return r;
}
__device__ __forceinline__ float rna_f(float x) { return __uint_as_float(rna_u(x)); }

__device__ __forceinline__ void ldsm4(uint32_t* r, uint32_t addr) {
    asm volatile("ldmatrix.sync.aligned.m8n8.x4.shared.b16 {%0,%1,%2,%3}, [%4];"
        : "=r"(r[0]), "=r"(r[1]), "=r"(r[2]), "=r"(r[3]) : "r"(addr));
}
__device__ __forceinline__ void mma8(float* c, const uint32_t* a, const uint32_t* b) {
    asm volatile(
        "mma.sync.aligned.m16n8k8.row.col.f32.tf32.tf32.f32 "
        "{%0,%1,%2,%3}, {%4,%5,%6,%7}, {%8,%9}, {%0,%1,%2,%3};"
        : "+f"(c[0]), "+f"(c[1]), "+f"(c[2]), "+f"(c[3])
        : "r"(a[0]), "r"(a[1]), "r"(a[2]), "r"(a[3]), "r"(b[0]), "r"(b[1]));
}
__device__ __forceinline__ void cpasync16(uint32_t s, const void* g) {
    asm volatile("cp.async.cg.shared.global [%0], [%1], 16;" :: "r"(s), "l"(g));
}
__device__ __forceinline__ void cpcommit() {
    asm volatile("cp.async.commit_group;" ::: "memory");
}
template<int N>
__device__ __forceinline__ void cpwait() {
    asm volatile("cp.async.wait_group %0;" :: "n"(N) : "memory");
}

// ---------------- tf32 mma GEMM body (cp.async 3-stage pipeline) ---------
// C[128,128]@(i0,j0) = alpha * A[.,K] @ B^T (+bias) (+C).
// A row-major [M,K], B row-major [N,K]. K % 16 == 0, K >= 32.
__device__ __forceinline__ void gemm_body(
    const float* __restrict__ A, const float* __restrict__ Bg,
    const float* __restrict__ bias, float* __restrict__ Cg,
    int Ncols, int Kdim, int i0, int j0,
    float alpha, int accum, int rndC)
{
    __shared__ __align__(16) float smA[3][128 * 16];
    __shared__ __align__(16) float smB[3][128 * 16];

    const int tid = threadIdx.x, lane = tid & 31, wid = tid >> 5;
    const int wm = (wid & 1) * 64, wn = (wid >> 1) * 32;

    float acc[4][4][4];
#pragma unroll
    for (int i = 0; i < 4; i++)
#pragma unroll
        for (int j = 0; j < 4; j++)
#pragma unroll
            for (int c = 0; c < 4; c++) acc[i][j][c] = 0.f;

    const uint32_t baseA = smem_u32(smA), baseB = smem_u32(smB);
    const uint32_t aoff = (uint32_t)((wm + (lane & 7) + (lane & 8)) * 64
                                     + ((lane >> 4) & 1) * 16);
    const uint32_t boff = (uint32_t)((wn + (lane & 7) + ((lane >> 4) & 1) * 8) * 64
                                     + ((lane >> 3) & 1) * 16);

    const int lr = tid >> 2, lkq = tid & 3;
    const uint32_t so0 = swz64(lr * 64 + lkq * 16);
    const uint32_t so1 = swz64((lr + 64) * 64 + lkq * 16);
    const float* aG = A + (long)i0 * Kdim + lkq * 4;
    const float* bG = Bg + (long)j0 * Kdim + lkq * 4;
    const int nkt = Kdim >> 4;

    auto issue = [&](int kt) {
        const uint32_t sb = (uint32_t)(kt % 3) * 8192;
        const int k0 = kt << 4;
        cpasync16(baseA + sb + so0, aG + (long)lr * Kdim + k0);
        cpasync16(baseA + sb + so1, aG + (long)(lr + 64) * Kdim + k0);
        cpasync16(baseB + sb + so0, bG + (long)lr * Kdim + k0);
        cpasync16(baseB + sb + so1, bG + (long)(lr + 64) * Kdim + k0);
        cpcommit();
    };

    issue(0);
    issue(1);
    cpwait<1>();
    __syncthreads();

    for (int kt = 0; kt < nkt; kt++) {
        const uint32_t stb = (uint32_t)(kt % 3) * 8192;
        if (kt + 2 < nkt) issue(kt + 2);

        const uint32_t sa = baseA + stb, sb = baseB + stb;
#pragma unroll
        for (int s = 0; s < 2; s++) {
            uint32_t af[4][4], bf[4][2];
#pragma unroll
            for (int mt = 0; mt < 4; mt++)
                ldsm4(af[mt], sa + swz64(aoff + mt * 1024 + s * 32));
#pragma unroll
            for (int p = 0; p < 2; p++) {
                uint32_t r[4];
                ldsm4(r, sb + swz64(boff + p * 1024 + s * 32));
                bf[2 * p][0] = r[0]; bf[2 * p][1] = r[1];
                bf[2 * p + 1][0] = r[2]; bf[2 * p + 1][1] = r[3];
            }
#pragma unroll
            for (int mt = 0; mt < 4; mt++)
#pragma unroll
                for (int nt = 0; nt < 4; nt++)
                    mma8(acc[mt][nt], af[mt], bf[nt]);
        }

        if (kt + 1 < nkt) {
            if (kt + 2 < nkt) cpwait<1>(); else cpwait<0>();
            __syncthreads();
        }
    }

    // epilogue
#pragma unroll
    for (int mt = 0; mt < 4; mt++) {
        int row = i0 + wm + mt * 16 + (lane >> 2);
#pragma unroll
        for (int nt = 0; nt < 4; nt++) {
            int col = j0 + wn + nt * 8 + (lane & 3) * 2;
            float bb0 = 0.f, bb1 = 0.f;
            if (bias) { bb0 = bias[col]; bb1 = bias[col + 1]; }
            long p0 = (long)row * Ncols + col;
            long p1 = (long)(row + 8) * Ncols + col;
            float v0 = acc[mt][nt][0] * alpha + bb0;
            float v1 = acc[mt][nt][1] * alpha + bb1;
            float v2 = acc[mt][nt][2] * alpha + bb0;
            float v3 = acc[mt][nt][3] * alpha + bb1;
            if (accum) {
                float2 c0 = *(float2*)&Cg[p0];
                float2 c1 = *(float2*)&Cg[p1];
                v0 += c0.x; v1 += c0.y; v2 += c1.x; v3 += c1.y;
            }
            if (rndC) { v0 = rna_f(v0); v1 = rna_f(v1); v2 = rna_f(v2); v3 = rna_f(v3); }
            *(float2*)&Cg[p0] = make_float2(v0, v1);
            *(float2*)&Cg[p1] = make_float2(v2, v3);
        }
    }
}

// generic strided wrapper
__global__ __launch_bounds__(256)
void gemm_lin(const float* __restrict__ A, const float* __restrict__ Bg,
              const float* __restrict__ bias, float* __restrict__ Cg,
              int Ncols, int Kdim, long sA, long sB, long sC,
              float alpha, int accum, int rndC)
{
    gemm_body(A + (long)blockIdx.z * sA, Bg + (long)blockIdx.z * sB, bias,
              Cg + (long)blockIdx.z * sC, Ncols, Kdim,
              blockIdx.y * 128, blockIdx.x * 128, alpha, accum, rndC);
}

// QK^T for all 6 (m,n) pairs: z = p*16 + b
__global__ __launch_bounds__(256)
void gemm_qk(const float* __restrict__ Q, const float* __restrict__ K,
             float* __restrict__ S6)
{
    int z = blockIdx.z, p = z >> 4, b = z & 15, m = p >> 1, j = p & 1;
    int n = j + (j >= m);
    gemm_body(Q + (long)m * BND + (long)b * ND,
              K + (long)n * BND + (long)b * ND, nullptr,
              S6 + ((long)p * 16 + b) * NN2,
              Nn, Dd, blockIdx.y * 128, blockIdx.x * 128, 0.0625f, 0, 0);
}

// PV for all 6 pairs -> per-pair msg buffers (no accumulation races)
__global__ __launch_bounds__(256)
void gemm_pv(const float* __restrict__ S6, const float* __restrict__ VT,
             float* __restrict__ msg)
{
    int z = blockIdx.z, p = z >> 4, b = z & 15, m = p >> 1, j = p & 1;
    int n = j + (j >= m);
    gemm_body(S6 + ((long)p * 16 + b) * NN2,
              VT + (long)n * BND + (long)b * ND, nullptr,
              msg + (long)p * BND + (long)b * ND,
              Dd, Nn, blockIdx.y * 128, blockIdx.x * 128, 1.f, 0, 0);
}

// ---------------- pre-round x to tf32 ------------------------------------
__global__ void round3_kernel(const float* __restrict__ a, const float* __restrict__ b,
                              const float* __restrict__ c, float* __restrict__ dst)
{
    long i = (long)blockIdx.x * blockDim.x + threadIdx.x;
    long stride = (long)gridDim.x * blockDim.x;
    for (; i < BND; i += stride) {
        dst[i]            = rna_f(a[i]);
        dst[BND + i]      = rna_f(b[i]);
        dst[2L * BND + i] = rna_f(c[i]);
    }
}

// ---------------- transpose (dst[C][R] = src[R][C]), tf32-rounded ---------
__global__ void transpose_kernel(const float* __restrict__ src, float* __restrict__ dst,
                                 int R, int C, long sS, long sD)
{
    __shared__ float t[32][33];
    src += (long)blockIdx.z * sS;
    dst += (long)blockIdx.z * sD;
    int c = blockIdx.x * 32 + threadIdx.x;
    int r0 = blockIdx.y * 32;
    for (int j = threadIdx.y; j < 32; j += 8)
        t[j][threadIdx.x] = src[(long)(r0 + j) * C + c];
    __syncthreads();
    int rr = blockIdx.y * 32 + threadIdx.x;
    int cc0 = blockIdx.x * 32;
    for (int j = threadIdx.y; j < 32; j += 8)
        dst[(long)(cc0 + j) * R + rr] = rna_f(t[threadIdx.x][j]);
}

// 5 weight transposes in one launch (z selects matrix)
__global__ void transpose_w5(const float* w0, const float* w1, const float* w2,
                             const float* w3, const float* w4, float* __restrict__ dst)
{
    __shared__ float t[32][33];
    const float* src = (blockIdx.z == 0) ? w0 : (blockIdx.z == 1) ? w1 :
                       (blockIdx.z == 2) ? w2 : (blockIdx.z == 3) ? w3 : w4;
    dst += (long)blockIdx.z * Dd * Dd;
    int c = blockIdx.x * 32 + threadIdx.x;
    int r0 = blockIdx.y * 32;
    for (int j = threadIdx.y; j < 32; j += 8)
        t[j][threadIdx.x] = src[(long)(r0 + j) * Dd + c];
    __syncthreads();
    int rr = blockIdx.y * 32 + threadIdx.x;
    int cc0 = blockIdx.x * 32;
    for (int j = threadIdx.y; j < 32; j += 8)
        dst[(long)(cc0 + j) * Dd + rr] = rna_f(t[threadIdx.x][j]);
}

// ---------------- fast deterministic CSR build ----------------------------
__global__ void zero_cnt_kernel(int* ncnt, int* ecnt)
{
    int i = blockIdx.x * blockDim.x + threadIdx.x;
    if (i < 3 * Nn) ncnt[i] = 0;
    if (i < 3 * Mm) ecnt[i] = 0;
}

__global__ void csr_count_kernel(const int* __restrict__ i0, const int* __restrict__ i1,
                                 const int* __restrict__ i2, int cnt_stride, int edge_off,
                                 int* __restrict__ cnt)
{
    const int* idx = (blockIdx.y == 0) ? i0 : (blockIdx.y == 1) ? i1 : i2;
    int c = blockIdx.x * blockDim.x + threadIdx.x;
    atomicAdd(&cnt[blockIdx.y * cnt_stride + idx[edge_off + c]], 1);
}

__global__ void csr_scan_kernel(const int* __restrict__ cnt, int* __restrict__ off, int nseg)
{
    __shared__ int buf[1024];
    int tid = threadIdx.x;
    int v = (tid < nseg) ? cnt[blockIdx.x * nseg + tid] : 0;
    buf[tid] = v;
    __syncthreads();
    for (int o = 1; o < nseg; o <<= 1) {
        int t = (tid >= o) ? buf[tid - o] : 0;
        __syncthreads();
        buf[tid] += t;
        __syncthreads();
    }
    if (tid < nseg) off[blockIdx.x * nseg + tid] = buf[tid] - v;
}

__global__ void csr_fill_kernel(const int* __restrict__ i0, const int* __restrict__ i1,
                                const int* __restrict__ i2, int nseg, int edge_off,
                                const int* __restrict__ off, int* __restrict__ list)
{
    __shared__ int sidx[Cc];
    const int* idx = (blockIdx.y == 0) ? i0 : (blockIdx.y == 1) ? i1 : i2;
    int tid = threadIdx.x;
    for (int i = tid; i < Cc; i += blockDim.x) sidx[i] = idx[edge_off + i];
    __syncthreads();

    int w = tid >> 5, lane = tid & 31;
    int s = blockIdx.x * 8 + w;
    if (s >= nseg) return;
    int p = off[blockIdx.y * nseg + s];
    int* lst = list + blockIdx.y * Cc;
    for (int c0 = 0; c0 < Cc; c0 += 32) {
        int c = c0 + lane;
        bool m = (sidx[c] == s);
        unsigned bal = __ballot_sync(0xffffffffu, m);
        if (m) lst[p + __popc(bal & ((1u << lane) - 1u))] = c;
        p += __popc(bal);
    }
}

// ---------------- sparse stage kernels (z = modality) ---------------------
__global__ void edge_sum_kernel(const float* __restrict__ xp,
                                const int* __restrict__ h0, const int* __restrict__ h1,
                                const int* __restrict__ h2,
                                const int* __restrict__ ecnt, const int* __restrict__ eoff,
                                const int* __restrict__ elist, float* __restrict__ es)
{
    int mmod = blockIdx.z;
    const int* hidx = (mmod == 0) ? h0 : (mmod == 1) ? h1 : h2;
    xp += (long)mmod * BND;
    es += (long)mmod * Mm * Bdim * Dd;
    ecnt += mmod * Mm; eoff += mmod * Mm; elist += mmod * Cc;

    int e = blockIdx.x, b = blockIdx.y, d = threadIdx.x;
    int cnt = ecnt[e], off = eoff[e];
    float s = 0.f;
    for (int i = 0; i < cnt; i++) {
        int c = elist[off + i];
        int node = hidx[c];
        s += xp[((long)b * Nn + node) * Dd + d];
    }
    es[((long)e * Bdim + b) * Dd + d] = s;
}

__global__ void logits_kernel(const float* __restrict__ xp, const float* __restrict__ es,
                              const int* __restrict__ h0, const int* __restrict__ h1,
                              const int* __restrict__ h2,
                              const float* __restrict__ att, float* __restrict__ e_out)
{
    int mmod = blockIdx.y;
    const int* hidx = (mmod == 0) ? h0 : (mmod == 1) ? h1 : h2;
    xp += (long)mmod * BND;
    es += (long)mmod * Mm * Bdim * Dd;
    e_out += (long)mmod * Cc * Bdim;

    int c = blockIdx.x;
    int node = hidx[c], edge = hidx[Cc + c];
    __shared__ float satt[2 * Dd];
    int tid = threadIdx.x;
    satt[tid] = att[tid];
    satt[tid + Dd] = att[tid + Dd];
    __syncthreads();

    int w = tid >> 5, lane = tid & 31;
    for (int bb = w; bb < Bdim; bb += 8) {
        float s = 0.f;
#pragma unroll
        for (int i = 0; i < Dd / 32; i++) {
            int d = lane + 32 * i;
            s += xp[((long)bb * Nn + node) * Dd + d] * satt[d]
               + es[((long)edge * Bdim + bb) * Dd + d] * satt[Dd + d];
        }
#pragma unroll
        for (int o = 16; o; o >>= 1) s += __shfl_xor_sync(0xffffffffu, s, o);
        if (lane == 0) {
            float v = (s >= 0.f) ? s : NEG_SLOPE * s;
            e_out[c * Bdim + bb] = v;
        }
    }
}

__global__ void node_softmax(float* __restrict__ e, const int* __restrict__ ncnt,
                             const int* __restrict__ noff, const int* __restrict__ nlist)
{
    int mmod = blockIdx.y;
    e += (long)mmod * Cc * Bdim;
    ncnt += mmod * Nn; noff += mmod * Nn; nlist += mmod * Cc;

    int n = blockIdx.x, b = threadIdx.x;
    if (b >= Bdim) return;
    int cnt = ncnt[n];
    if (!cnt) return;
    int off = noff[n];
    float mx = -1e30f;
    for (int i = 0; i < cnt; i++) {
        int c = nlist[off + i];
        mx = fmaxf(mx, e[c * Bdim + b]);
    }
    float sum = 0.f;
    for (int i = 0; i < cnt; i++) {
        int c = nlist[off + i];
        float v = expf(e[c * Bdim + b] - mx);
        e[c * Bdim + b] = v;
        sum += v;
    }
    float inv = 1.f / (sum + 1e-16f);
    for (int i = 0; i < cnt; i++) {
        int c = nlist[off + i];
        e[c * Bdim + b] *= inv;
    }
}

__global__ void xedge_kernel(const float* __restrict__ xp, const float* __restrict__ alpha,
                             const int* __restrict__ h0, const int* __restrict__ h1,
                             const int* __restrict__ h2,
                             const int* __restrict__ ecnt, const int* __restrict__ eoff,
                             const int* __restrict__ elist, float* __restrict__ xe)
{
    int mmod = blockIdx.z;
    const int* hidx = (mmod == 0) ? h0 : (mmod == 1) ? h1 : h2;
    xp += (long)mmod * BND;
    alpha += (long)mmod * Cc * Bdim;
    xe += (long)mmod * Mm * Bdim * Dd;
    ecnt += mmod * Mm; eoff += mmod * Mm; elist += mmod * Cc;

    int e = blockIdx.x, b = blockIdx.y, d = threadIdx.x;
    int cnt = ecnt[e];
    float s = 0.f;
    if (cnt) {
        int off = eoff[e];
        for (int i = 0; i < cnt; i++) {
            int c = elist[off + i];
            int node = hidx[c];
            s += alpha[c * Bdim + b] * xp[((long)b * Nn + node) * Dd + d];
        }
        s /= (float)cnt;
    }
    xe[((long)e * Bdim + b) * Dd + d] = s;
}

// h output rounded to tf32 (GEMM A-operand downstream)
__global__ void xnode_kernel(const float* __restrict__ xe, const float* __restrict__ alpha,
                             const int* __restrict__ h0, const int* __restrict__ h1,
                             const int* __restrict__ h2,
                             const int* __restrict__ ncnt, const int* __restrict__ noff,
                             const int* __restrict__ nlist, float* __restrict__ h)
{
    int mmod = blockIdx.z;
    const int* hidx = (mmod == 0) ? h0 : (mmod == 1) ? h1 : h2;
    xe += (long)mmod * Mm * Bdim * Dd;
    alpha += (long)mmod * Cc * Bdim;
    h += (long)mmod * BND;
    ncnt += mmod * Nn; noff += mmod * Nn; nlist += mmod * Cc;

    int n = blockIdx.x, b = blockIdx.y, d = threadIdx.x;
    int cnt = ncnt[n];
    float s = 0.f;
    if (cnt) {
        int off = noff[n];
        for (int i = 0; i < cnt; i++) {
            int c = nlist[off + i];
            int eidx = hidx[Cc + c];
            s += alpha[c * Bdim + b] * xe[((long)eidx * Bdim + b) * Dd + d];
        }
        s /= (float)cnt;
    }
    h[((long)b * Nn + n) * Dd + d] = rna_f(s);
}

// ---------------- row softmax over 1024-wide rows (tf32-rounded output) ---
__global__ void softmax_rows(float* __restrict__ S)
{
    long row = blockIdx.x;
    float* p = S + row * 1024;
    int tid = threadIdx.x;
    float v[4];
    float mx = -1e30f;
#pragma unroll
    for (int i = 0; i < 4; i++) {
        v[i] = p[tid + 256 * i];
        mx = fmaxf(mx, v[i]);
    }
    __shared__ float red[256];
    red[tid] = mx;
    __syncthreads();
    for (int o = 128; o; o >>= 1) {
        if (tid < o) red[tid] = fmaxf(red[tid], red[tid + o]);
        __syncthreads();
    }
    mx = red[0];
    __syncthreads();
    float s = 0.f;
#pragma unroll
    for (int i = 0; i < 4; i++) {
        v[i] = __expf(v[i] - mx);
        s += v[i];
    }
    red[tid] = s;
    __syncthreads();
    for (int o = 128; o; o >>= 1) {
        if (tid < o) red[tid] += red[tid + o];
        __syncthreads();
    }
    float inv = 1.f / red[0];
#pragma unroll
    for (int i = 0; i < 4; i++) p[tid + 256 * i] = rna_f(v[i] * inv);
}

// ---------------- out = relu(base + msg_pair0 + msg_pair1) ----------------
__global__ void relu_final(float* __restrict__ out, const float* __restrict__ msg)
{
    long i = (long)blockIdx.x * blockDim.x + threadIdx.x;
    long stride = (long)gridDim.x * blockDim.x;
    for (; i < BND; i += stride) {
#pragma unroll
        for (int m = 0; m < 3; m++) {
            long o = (long)m * BND + i;
            float v = out[o] + msg[(long)(2 * m) * BND + i]
                             + msg[(long)(2 * m + 1) * BND + i];
            out[o] = fmaxf(v, 0.f);
        }
    }
}

// ---------------- launcher -------------------------------------------------
extern "C" void kernel_launch(void* const* d_in, const int* in_sizes, int n_in,
                              void* d_out, int out_size)
{
    const float* x[3]    = {(const float*)d_in[0], (const float*)d_in[1], (const float*)d_in[2]};
    const int*   hidx[3] = {(const int*)d_in[3], (const int*)d_in[4], (const int*)d_in[5]};
    const float* W_hg = (const float*)d_in[6];
    const float* att  = (const float*)d_in[7];
    const float* WQ = (const float*)d_in[8];
    const float* bQ = (const float*)d_in[9];
    const float* WK = (const float*)d_in[10];
    const float* bK = (const float*)d_in[11];
    const float* WV = (const float*)d_in[12];
    const float* bV = (const float*)d_in[13];
    const float* WO = (const float*)d_in[14];
    const float* bO = (const float*)d_in[15];
    float* out = (float*)d_out;

    float *xp, *h, *Q, *Kb, *Vb, *VT, *WT, *S6, *msg, *es, *xe, *ealpha;
    int *ncnt, *noff, *nlist, *ecnt, *eoff, *elist;
    cudaGetSymbolAddress((void**)&xp, g_xp);
    cudaGetSymbolAddress((void**)&h,  g_h);
    cudaGetSymbolAddress((void**)&Q,  g_Q);
    cudaGetSymbolAddress((void**)&Kb, g_Kb);
    cudaGetSymbolAddress((void**)&Vb, g_Vb);
    cudaGetSymbolAddress((void**)&VT, g_VT);
    cudaGetSymbolAddress((void**)&WT, g_WT);
    cudaGetSymbolAddress((void**)&S6, g_S6);
    cudaGetSymbolAddress((void**)&msg, g_msg);
    cudaGetSymbolAddress((void**)&es, g_es);
    cudaGetSymbolAddress((void**)&xe, g_xe);
    cudaGetSymbolAddress((void**)&ealpha, g_e);
    cudaGetSymbolAddress((void**)&ncnt, g_ncnt);
    cudaGetSymbolAddress((void**)&noff, g_noff);
    cudaGetSymbolAddress((void**)&nlist, g_nlist);
    cudaGetSymbolAddress((void**)&ecnt, g_ecnt);
    cudaGetSymbolAddress((void**)&eoff, g_eoff);
    cudaGetSymbolAddress((void**)&elist, g_elist);

    const int DD = Dd * Dd;

    // 0) weight transposes (tf32-rounded) + pre-round x into Q staging
    transpose_w5<<<dim3(8, 8, 5), dim3(32, 8)>>>(W_hg, WQ, WK, WV, WO, WT);
    round3_kernel<<<4096, 256>>>(x[0], x[1], x[2], Q);

    // 1) xp = x @ W_hg, all 3 modalities in one launch
    gemm_lin<<<dim3(2, 128, 3), 256>>>(Q, WT + 0 * DD, nullptr, xp,
                                       Dd, Dd, BND, 0, BND, 1.f, 0, 0);

    // 2) CSR build (parallel, deterministic: lists sorted by c)
    zero_cnt_kernel<<<4, 1024>>>(ncnt, ecnt);
    csr_count_kernel<<<dim3(Cc / 256, 3), 256>>>(hidx[0], hidx[1], hidx[2], Nn, 0,  ncnt);
    csr_count_kernel<<<dim3(Cc / 256, 3), 256>>>(hidx[0], hidx[1], hidx[2], Mm, Cc, ecnt);
    csr_scan_kernel<<<3, 1024>>>(ncnt, noff, Nn);
    csr_scan_kernel<<<3, 1024>>>(ecnt, eoff, Mm);
    csr_fill_kernel<<<dim3(Nn / 8, 3), 256>>>(hidx[0], hidx[1], hidx[2], Nn, 0,  noff, nlist);
    csr_fill_kernel<<<dim3(Mm / 8, 3), 256>>>(hidx[0], hidx[1], hidx[2], Mm, Cc, eoff, elist);

    // 3-7) sparse hypergraph pipeline, modalities batched via gridDim.z/.y
    edge_sum_kernel<<<dim3(Mm, Bdim, 3), Dd>>>(xp, hidx[0], hidx[1], hidx[2],
                                               ecnt, eoff, elist, es);
    logits_kernel<<<dim3(Cc, 3), 256>>>(xp, es, hidx[0], hidx[1], hidx[2], att, ealpha);
    node_softmax<<<dim3(Nn, 3), 32>>>(ealpha, ncnt, noff, nlist);
    xedge_kernel<<<dim3(Mm, Bdim, 3), Dd>>>(xp, ealpha, hidx[0], hidx[1], hidx[2],
                                            ecnt, eoff, elist, xe);
    xnode_kernel<<<dim3(Nn, Bdim, 3), Dd>>>(xe, ealpha, hidx[0], hidx[1], hidx[2],
                                            ncnt, noff, nlist, h);

    // 8) projections ([49152,256] @ [256,256]); Q,K rounded for reuse as operands
    gemm_lin<<<dim3(2, 384, 1), 256>>>(h, WT + 1 * DD, bQ, Q,  Dd, Dd, 0, 0, 0, 1.f, 0, 1);
    gemm_lin<<<dim3(2, 384, 1), 256>>>(h, WT + 2 * DD, bK, Kb, Dd, Dd, 0, 0, 0, 1.f, 0, 1);
    gemm_lin<<<dim3(2, 384, 1), 256>>>(h, WT + 3 * DD, bV, Vb, Dd, Dd, 0, 0, 0, 1.f, 0, 0);
    // base: out = h @ WO + bO
    gemm_lin<<<dim3(2, 384, 1), 256>>>(h, WT + 4 * DD, bO, out, Dd, Dd, 0, 0, 0, 1.f, 0, 0);

    // 8b) VT[z][d][n] = V[z][n][d] per (modality,batch) slice, tf32-rounded
    transpose_kernel<<<dim3(Dd / 32, Nn / 32, 48), dim3(32, 8)>>>(Vb, VT, Nn, Dd, ND, ND);

    // 9) cross-modal attention, all 6 pairs per stage in single launches
    gemm_qk<<<dim3(8, 8, 96), 256>>>(Q, Kb, S6);
    softmax_rows<<<6 * Bdim * Nn, 256>>>(S6);
    gemm_pv<<<dim3(2, 8, 96), 256>>>(S6, VT, msg);

    // 10) final combine + relu
    relu_final<<<4096, 256>>>(out, msg);
}

// round 7
// speedup vs baseline: 4.6535x; 1.1919x over previous
#include <cuda_runtime.h>
#include <stdint.h>
#include <math.h>

// Problem constants
#define Bdim 16
#define Nn   1024
#define Dd   256
#define Mm   128
#define Cc   8192
#define NEG_SLOPE 0.2f

#define BND (Bdim * Nn * Dd)                 // 4,194,304 (per modality)
#define ND  (Nn * Dd)                        // per-batch stride
#define NN2 (Nn * Nn)

#define GEMM_SMEM 98304                      // 3 stages x 32KB

// ---------------- scratch (device globals; no allocation) ----------------
__device__ float g_xp[3 * BND];              // projected inputs
__device__ float g_h [3 * BND];              // hypergraph outputs (tf32-rounded)
__device__ float g_Q [3 * BND];              // also used as rounded-x staging
__device__ float g_Kb[3 * BND];
__device__ float g_Vb[3 * BND];
__device__ float g_VT[3 * BND];              // V transposed per (mod,batch), tf32-rounded
__device__ float g_WT[5 * Dd * Dd];          // W_hg,WQ,WK,WV,WO transposed+rounded
__device__ float g_S6[6L * Bdim * Nn * Nn];  // attention scores, all 6 pairs
__device__ float g_msg[6L * BND];            // per-pair PV outputs
__device__ float g_es[3 * Mm * Bdim * Dd];
__device__ float g_xe[3 * Mm * Bdim * Dd];
__device__ float g_e [3 * Cc * Bdim];
__device__ float g_p1[3 * Bdim * Nn];        // dot(xp, att1)
__device__ float g_p2[3 * Mm * Bdim];        // dot(es, att2)
__device__ int   g_ncnt[3 * Nn], g_noff[3 * Nn], g_nlist[3 * Cc];
__device__ int   g_ecnt[3 * Mm], g_eoff[3 * Mm], g_elist[3 * Cc];

// ---------------- helpers -------------------------------------------------
__device__ __forceinline__ uint32_t smem_u32(const void* p) {
    uint32_t a;
    asm("{ .reg .u64 t; cvta.to.shared.u64 t, %1; cvt.u32.u64 %0, t; }"
        : "=r"(a) : "l"(p));
    return a;
}
__device__ __forceinline__ uint32_t swz128(uint32_t off) {
    return off ^ ((off >> 3) & 0x70);
}
__device__ __forceinline__ uint32_t rna_u(float x) {
    uint32_t r;
    asm("cvt.rna.tf32.f32 %0, %1;" : "=r"(r) : "f"(x));
    return r;
}
__device__ __forceinline__ float rna_f(float x) { return __uint_as_float(rna_u(x)); }

__device__ __forceinline__ void ldsm4(uint32_t* r, uint32_t addr) {
    asm volatile("ldmatrix.sync.aligned.m8n8.x4.shared.b16 {%0,%1,%2,%3}, [%4];"
        : "=r"(r[0]), "=r"(r[1]), "=r"(r[2]), "=r"(r[3]) : "r"(addr));
}
__device__ __forceinline__ void mma8(float* c, const uint32_t* a, const uint32_t* b) {
    asm volatile(
        "mma.sync.aligned.m16n8k8.row.col.f32.tf32.tf32.f32 "
        "{%0,%1,%2,%3}, {%4,%5,%6,%7}, {%8,%9}, {%0,%1,%2,%3};"
        : "+f"(c[0]), "+f"(c[1]), "+f"(c[2]), "+f"(c[3])
        : "r"(a[0]), "r"(a[1]), "r"(a[2]), "r"(a[3]), "r"(b[0]), "r"(b[1]));
}
__device__ __forceinline__ void cpasync16(uint32_t s, const void* g) {
    asm volatile("cp.async.cg.shared.global [%0], [%1], 16;" :: "r"(s), "l"(g));
}
__device__ __forceinline__ void cpcommit() {
    asm volatile("cp.async.commit_group;" ::: "memory");
}
template<int N>
__device__ __forceinline__ void cpwait() {
    asm volatile("cp.async.wait_group %0;" :: "n"(N) : "memory");
}

// ---------------- tf32 mma GEMM body (BK=32, 3-stage cp.async) -----------
// C[128,128]@(i0,j0) = alpha * A[.,K] @ B^T (+bias) (+C).
// A row-major [M,K], B row-major [N,K]. K % 32 == 0, K >= 64.
// Stage layout in dynamic smem: stage s at s*32768: A tile (128x32f, 16KB,
// 128B rows SW128-swizzled), then B tile at +16384.
__device__ __forceinline__ void gemm_body(
    const float* __restrict__ A, const float* __restrict__ Bg,
    const float* __restrict__ bias, float* __restrict__ Cg,
    int Ncols, int Kdim, int i0, int j0,
    float alpha, int accum, int rndC)
{
    extern __shared__ float smem[];

    const int tid = threadIdx.x, lane = tid & 31, wid = tid >> 5;
    const int wm = (wid & 1) * 64, wn = (wid >> 1) * 32;

    float acc[4][4][4];
#pragma unroll
    for (int i = 0; i < 4; i++)
#pragma unroll
        for (int j = 0; j < 4; j++)
#pragma unroll
            for (int c = 0; c < 4; c++) acc[i][j][c] = 0.f;

    const uint32_t base = smem_u32(smem);
    const uint32_t aoff = (uint32_t)((wm + (lane & 7) + (lane & 8)) * 128
                                     + ((lane >> 4) & 1) * 16);
    const uint32_t boff = (uint32_t)((wn + (lane & 7) + ((lane >> 4) & 1) * 8) * 128
                                     + ((lane >> 3) & 1) * 16);

    const int lr = tid >> 3, lkq = tid & 7;      // 32 rows/step, 8 quads/row
    uint32_t so[4];
#pragma unroll
    for (int q = 0; q < 4; q++)
        so[q] = swz128((lr + q * 32) * 128 + lkq * 16);
    const float* aG = A + (long)(i0 + lr) * Kdim + lkq * 4;
    const float* bG = Bg + (long)(j0 + lr) * Kdim + lkq * 4;
    const int nkt = Kdim >> 5;

    auto issue = [&](int kt) {
        const uint32_t sb = base + (uint32_t)(kt % 3) * 32768;
        const long k0 = (long)(kt << 5);
#pragma unroll
        for (int q = 0; q < 4; q++)
            cpasync16(sb + so[q], aG + (long)(q * 32) * Kdim + k0);
#pragma unroll
        for (int q = 0; q < 4; q++)
            cpasync16(sb + 16384 + so[q], bG + (long)(q * 32) * Kdim + k0);
        cpcommit();
    };

    issue(0);
    issue(1);
    cpwait<1>();
    __syncthreads();

    for (int kt = 0; kt < nkt; kt++) {
        const uint32_t stb = base + (uint32_t)(kt % 3) * 32768;
        if (kt + 2 < nkt) issue(kt + 2);

        const uint32_t sa = stb, sb = stb + 16384;
#pragma unroll
        for (int s = 0; s < 4; s++) {
            uint32_t af[4][4], bf[4][2];
#pragma unroll
            for (int mt = 0; mt < 4; mt++)
                ldsm4(af[mt], sa + swz128(aoff + mt * 2048 + s * 32));
#pragma unroll
            for (int p = 0; p < 2; p++) {
                uint32_t r[4];
                ldsm4(r, sb + swz128(boff + p * 2048 + s * 32));
                bf[2 * p][0] = r[0]; bf[2 * p][1] = r[1];
                bf[2 * p + 1][0] = r[2]; bf[2 * p + 1][1] = r[3];
            }
#pragma unroll
            for (int mt = 0; mt < 4; mt++)
#pragma unroll
                for (int nt = 0; nt < 4; nt++)
                    mma8(acc[mt][nt], af[mt], bf[nt]);
        }

        if (kt + 1 < nkt) {
            if (kt + 2 < nkt) cpwait<1>(); else cpwait<0>();
            __syncthreads();
        }
    }

    // epilogue
#pragma unroll
    for (int mt = 0; mt < 4; mt++) {
        int row = i0 + wm + mt * 16 + (lane >> 2);
#pragma unroll
        for (int nt = 0; nt < 4; nt++) {
            int col = j0 + wn + nt * 8 + (lane & 3) * 2;
            float bb0 = 0.f, bb1 = 0.f;
            if (bias) { bb0 = bias[col]; bb1 = bias[col + 1]; }
            long p0 = (long)row * Ncols + col;
            long p1 = (long)(row + 8) * Ncols + col;
            float v0 = acc[mt][nt][0] * alpha + bb0;
            float v1 = acc[mt][nt][1] * alpha + bb1;
            float v2 = acc[mt][nt][2] * alpha + bb0;
            float v3 = acc[mt][nt][3] * alpha + bb1;
            if (accum) {
                float2 c0 = *(float2*)&Cg[p0];
                float2 c1 = *(float2*)&Cg[p1];
                v0 += c0.x; v1 += c0.y; v2 += c1.x; v3 += c1.y;
            }
            if (rndC) { v0 = rna_f(v0); v1 = rna_f(v1); v2 = rna_f(v2); v3 = rna_f(v3); }
            *(float2*)&Cg[p0] = make_float2(v0, v1);
            *(float2*)&Cg[p1] = make_float2(v2, v3);
        }
    }
}

// generic strided wrapper
__global__ __launch_bounds__(256, 2)
void gemm_lin(const float* __restrict__ A, const float* __restrict__ Bg,
              const float* __restrict__ bias, float* __restrict__ Cg,
              int Ncols, int Kdim, long sA, long sB, long sC,
              float alpha, int accum, int rndC)
{
    gemm_body(A + (long)blockIdx.z * sA, Bg + (long)blockIdx.z * sB, bias,
              Cg + (long)blockIdx.z * sC, Ncols, Kdim,
              blockIdx.y * 128, blockIdx.x * 128, alpha, accum, rndC);
}

// QK^T for all 6 (m,n) pairs: z = p*16 + b
__global__ __launch_bounds__(256, 2)
void gemm_qk(const float* __restrict__ Q, const float* __restrict__ K,
             float* __restrict__ S6)
{
    int z = blockIdx.z, p = z >> 4, b = z & 15, m = p >> 1, j = p & 1;
    int n = j + (j >= m);
    gemm_body(Q + (long)m * BND + (long)b * ND,
              K + (long)n * BND + (long)b * ND, nullptr,
              S6 + ((long)p * 16 + b) * NN2,
              Nn, Dd, blockIdx.y * 128, blockIdx.x * 128, 0.0625f, 0, 0);
}

// PV for all 6 pairs -> per-pair msg buffers (no accumulation races)
__global__ __launch_bounds__(256, 2)
void gemm_pv(const float* __restrict__ S6, const float* __restrict__ VT,
             float* __restrict__ msg)
{
    int z = blockIdx.z, p = z >> 4, b = z & 15, m = p >> 1, j = p & 1;
    int n = j + (j >= m);
    gemm_body(S6 + ((long)p * 16 + b) * NN2,
              VT + (long)n * BND + (long)b * ND, nullptr,
              msg + (long)p * BND + (long)b * ND,
              Dd, Nn, blockIdx.y * 128, blockIdx.x * 128, 1.f, 0, 0);
}

// ---------------- pre-round x to tf32 ------------------------------------
__global__ void round3_kernel(const float* __restrict__ a, const float* __restrict__ b,
                              const float* __restrict__ c, float* __restrict__ dst)
{
    long i = (long)blockIdx.x * blockDim.x + threadIdx.x;
    long stride = (long)gridDim.x * blockDim.x;
    for (; i < BND; i += stride) {
        dst[i]            = rna_f(a[i]);
        dst[BND + i]      = rna_f(b[i]);
        dst[2L * BND + i] = rna_f(c[i]);
    }
}

// ---------------- transpose (dst[C][R] = src[R][C]), tf32-rounded ---------
__global__ void transpose_kernel(const float* __restrict__ src, float* __restrict__ dst,
                                 int R, int C, long sS, long sD)
{
    __shared__ float t[32][33];
    src += (long)blockIdx.z * sS;
    dst += (long)blockIdx.z * sD;
    int c = blockIdx.x * 32 + threadIdx.x;
    int r0 = blockIdx.y * 32;
    for (int j = threadIdx.y; j < 32; j += 8)
        t[j][threadIdx.x] = src[(long)(r0 + j) * C + c];
    __syncthreads();
    int rr = blockIdx.y * 32 + threadIdx.x;
    int cc0 = blockIdx.x * 32;
    for (int j = threadIdx.y; j < 32; j += 8)
        dst[(long)(cc0 + j) * R + rr] = rna_f(t[threadIdx.x][j]);
}

// 5 weight transposes in one launch (z selects matrix)
__global__ void transpose_w5(const float* w0, const float* w1, const float* w2,
                             const float* w3, const float* w4, float* __restrict__ dst)
{
    __shared__ float t[32][33];
    const float* src = (blockIdx.z == 0) ? w0 : (blockIdx.z == 1) ? w1 :
                       (blockIdx.z == 2) ? w2 : (blockIdx.z == 3) ? w3 : w4;
    dst += (long)blockIdx.z * Dd * Dd;
    int c = blockIdx.x * 32 + threadIdx.x;
    int r0 = blockIdx.y * 32;
    for (int j = threadIdx.y; j < 32; j += 8)
        t[j][threadIdx.x] = src[(long)(r0 + j) * Dd + c];
    __syncthreads();
    int rr = blockIdx.y * 32 + threadIdx.x;
    int cc0 = blockIdx.x * 32;
    for (int j = threadIdx.y; j < 32; j += 8)
        dst[(long)(cc0 + j) * Dd + rr] = rna_f(t[threadIdx.x][j]);
}

// ---------------- fast deterministic CSR build ----------------------------
__global__ void zero_cnt_kernel(int* ncnt, int* ecnt)
{
    int i = blockIdx.x * blockDim.x + threadIdx.x;
    if (i < 3 * Nn) ncnt[i] = 0;
    if (i < 3 * Mm) ecnt[i] = 0;
}

__global__ void csr_count_kernel(const int* __restrict__ i0, const int* __restrict__ i1,
                                 const int* __restrict__ i2, int cnt_stride, int edge_off,
                                 int* __restrict__ cnt)
{
    const int* idx = (blockIdx.y == 0) ? i0 : (blockIdx.y == 1) ? i1 : i2;
    int c = blockIdx.x * blockDim.x + threadIdx.x;
    atomicAdd(&cnt[blockIdx.y * cnt_stride + idx[edge_off + c]], 1);
}

__global__ void csr_scan_kernel(const int* __restrict__ cnt, int* __restrict__ off, int nseg)
{
    __shared__ int buf[1024];
    int tid = threadIdx.x;
    int v = (tid < nseg) ? cnt[blockIdx.x * nseg + tid] : 0;
    buf[tid] = v;
    __syncthreads();
    for (int o = 1; o < nseg; o <<= 1) {
        int t = (tid >= o) ? buf[tid - o] : 0;
        __syncthreads();
        buf[tid] += t;
        __syncthreads();
    }
    if (tid < nseg) off[blockIdx.x * nseg + tid] = buf[tid] - v;
}

__global__ void csr_fill_kernel(const int* __restrict__ i0, const int* __restrict__ i1,
                                const int* __restrict__ i2, int nseg, int edge_off,
                                const int* __restrict__ off, int* __restrict__ list)
{
    __shared__ int sidx[Cc];
    const int* idx = (blockIdx.y == 0) ? i0 : (blockIdx.y == 1) ? i1 : i2;
    int tid = threadIdx.x;
    for (int i = tid; i < Cc; i += blockDim.x) sidx[i] = idx[edge_off + i];
    __syncthreads();

    int w = tid >> 5, lane = tid & 31;
    int s = blockIdx.x * 8 + w;
    if (s >= nseg) return;
    int p = off[blockIdx.y * nseg + s];
    int* lst = list + blockIdx.y * Cc;
    for (int c0 = 0; c0 < Cc; c0 += 32) {
        int c = c0 + lane;
        bool m = (sidx[c] == s);
        unsigned bal = __ballot_sync(0xffffffffu, m);
        if (m) lst[p + __popc(bal & ((1u << lane) - 1u))] = c;
        p += __popc(bal);
    }
}

// ---------------- sparse stage kernels (z = modality) ---------------------
__global__ void edge_sum_kernel(const float* __restrict__ xp,
                                const int* __restrict__ h0, const int* __restrict__ h1,
                                const int* __restrict__ h2,
                                const int* __restrict__ ecnt, const int* __restrict__ eoff,
                                const int* __restrict__ elist, float* __restrict__ es)
{
    int mmod = blockIdx.z;
    const int* hidx = (mmod == 0) ? h0 : (mmod == 1) ? h1 : h2;
    xp += (long)mmod * BND;
    es += (long)mmod * Mm * Bdim * Dd;
    ecnt += mmod * Mm; eoff += mmod * Mm; elist += mmod * Cc;

    int e = blockIdx.x, b = blockIdx.y, d = threadIdx.x;
    int cnt = ecnt[e], off = eoff[e];
    float s = 0.f;
    for (int i = 0; i < cnt; i++) {
        int c = elist[off + i];
        int node = hidx[c];
        s += xp[((long)b * Nn + node) * Dd + d];
    }
    es[((long)e * Bdim + b) * Dd + d] = s;
}

// proj: p1[mod][row] = dot(xp[row,:], att[0:D]) for row < B*N;
//       p2[mod][r2]  = dot(es[r2,:],  att[D:2D]) for r2 = row - B*N
__global__ void proj_kernel(const float* __restrict__ xp, const float* __restrict__ es,
                            const float* __restrict__ att,
                            float* __restrict__ p1, float* __restrict__ p2)
{
    int mmod = blockIdx.y;
    int row = blockIdx.x * 8 + (threadIdx.x >> 5);
    int lane = threadIdx.x & 31;
    const float* src;
    const float* a;
    if (row < Bdim * Nn) {
        src = xp + (long)mmod * BND + (long)row * Dd;
        a = att;
    } else {
        src = es + (long)mmod * Mm * Bdim * Dd + (long)(row - Bdim * Nn) * Dd;
        a = att + Dd;
    }
    float s = 0.f;
#pragma unroll
    for (int i = 0; i < Dd / 32; i++) {
        int d = lane + 32 * i;
        s += src[d] * a[d];
    }
#pragma unroll
    for (int o = 16; o; o >>= 1) s += __shfl_xor_sync(0xffffffffu, s, o);
    if (lane == 0) {
        if (row < Bdim * Nn) p1[mmod * Bdim * Nn + row] = s;
        else                 p2[mmod * Mm * Bdim + row - Bdim * Nn] = s;
    }
}

// logits gather + leaky relu: e[c,b] = p1[b*N+node[c]] + p2[edge[c]*B+b]
__global__ void logits_gather(const int* __restrict__ h0, const int* __restrict__ h1,
                              const int* __restrict__ h2,
                              const float* __restrict__ p1, const float* __restrict__ p2,
                              float* __restrict__ e_out)
{
    int mmod = blockIdx.y;
    const int* hidx = (mmod == 0) ? h0 : (mmod == 1) ? h1 : h2;
    int i = blockIdx.x * blockDim.x + threadIdx.x;     // 0 .. Cc*Bdim-1
    int c = i >> 4, b = i & 15;
    float v = p1[mmod * Bdim * Nn + b * Nn + hidx[c]]
            + p2[mmod * Mm * Bdim + hidx[Cc + c] * Bdim + b];
    e_out[(long)mmod * Cc * Bdim + i] = (v >= 0.f) ? v : NEG_SLOPE * v;
}

__global__ void node_softmax(float* __restrict__ e, const int* __restrict__ ncnt,
                             const int* __restrict__ noff, const int* __restrict__ nlist)
{
    int mmod = blockIdx.y;
    e += (long)mmod * Cc * Bdim;
    ncnt += mmod * Nn; noff += mmod * Nn; nlist += mmod * Cc;

    int n = blockIdx.x, b = threadIdx.x;
    if (b >= Bdim) return;
    int cnt = ncnt[n];
    if (!cnt) return;
    int off = noff[n];
    float mx = -1e30f;
    for (int i = 0; i < cnt; i++) {
        int c = nlist[off + i];
        mx = fmaxf(mx, e[c * Bdim + b]);
    }
    float sum = 0.f;
    for (int i = 0; i < cnt; i++) {
        int c = nlist[off + i];
        float v = expf(e[c * Bdim + b] - mx);
        e[c * Bdim + b] = v;
        sum += v;
    }
    float inv = 1.f / (sum + 1e-16f);
    for (int i = 0; i < cnt; i++) {
        int c = nlist[off + i];
        e[c * Bdim + b] *= inv;
    }
}

__global__ void xedge_kernel(const float* __restrict__ xp, const float* __restrict__ alpha,
                             const int* __restrict__ h0, const int* __restrict__ h1,
                             const int* __restrict__ h2,
                             const int* __restrict__ ecnt, const int* __restrict__ eoff,
                             const int* __restrict__ elist, float* __restrict__ xe)
{
    int mmod = blockIdx.z;
    const int* hidx = (mmod == 0) ? h0 : (mmod == 1) ? h1 : h2;
    xp += (long)mmod * BND;
    alpha += (long)mmod * Cc * Bdim;
    xe += (long)mmod * Mm * Bdim * Dd;
    ecnt += mmod * Mm; eoff += mmod * Mm; elist += mmod * Cc;

    int e = blockIdx.x, b = blockIdx.y, d = threadIdx.x;
    int cnt = ecnt[e];
    float s = 0.f;
    if (cnt) {
        int off = eoff[e];
        for (int i = 0; i < cnt; i++) {
            int c = elist[off + i];
            int node = hidx[c];
            s += alpha[c * Bdim + b] * xp[((long)b * Nn + node) * Dd + d];
        }
        s /= (float)cnt;
    }
    xe[((long)e * Bdim + b) * Dd + d] = s;
}

// h output rounded to tf32 (GEMM A-operand downstream)
__global__ void xnode_kernel(const float* __restrict__ xe, const float* __restrict__ alpha,
                             const int* __restrict__ h0, const int* __restrict__ h1,
                             const int* __restrict__ h2,
                             const int* __restrict__ ncnt, const int* __restrict__ noff,
                             const int* __restrict__ nlist, float* __restrict__ h)
{
    int mmod = blockIdx.z;
    const int* hidx = (mmod == 0) ? h0 : (mmod == 1) ? h1 : h2;
    xe += (long)mmod * Mm * Bdim * Dd;
    alpha += (long)mmod * Cc * Bdim;
    h += (long)mmod * BND;
    ncnt += mmod * Nn; noff += mmod * Nn; nlist += mmod * Cc;

    int n = blockIdx.x, b = blockIdx.y, d = threadIdx.x;
    int cnt = ncnt[n];
    float s = 0.f;
    if (cnt) {
        int off = noff[n];
        for (int i = 0; i < cnt; i++) {
            int c = nlist[off + i];
            int eidx = hidx[Cc + c];
            s += alpha[c * Bdim + b] * xe[((long)eidx * Bdim + b) * Dd + d];
        }
        s /= (float)cnt;
    }
    h[((long)b * Nn + n) * Dd + d] = rna_f(s);
}

// ---------------- warp-per-row softmax over 1024-wide rows ----------------
__global__ void softmax_rows(float* __restrict__ S)
{
    long row = (long)blockIdx.x * 8 + (threadIdx.x >> 5);
    int lane = threadIdx.x & 31;
    float* p = S + row * 1024;
    float v[32];
    float mx = -1e30f;
#pragma unroll
    for (int i = 0; i < 32; i++) {
        v[i] = p[lane + 32 * i];
        mx = fmaxf(mx, v[i]);
    }
#pragma unroll
    for (int o = 16; o; o >>= 1) mx = fmaxf(mx, __shfl_xor_sync(0xffffffffu, mx, o));
    float s = 0.f;
#pragma unroll
    for (int i = 0; i < 32; i++) {
        v[i] = __expf(v[i] - mx);
        s += v[i];
    }
#pragma unroll
    for (int o = 16; o; o >>= 1) s += __shfl_xor_sync(0xffffffffu, s, o);
    float inv = 1.f / s;
#pragma unroll
    for (int i = 0; i < 32; i++) p[lane + 32 * i] = rna_f(v[i] * inv);
}

// ---------------- out = relu(base + msg_pair0 + msg_pair1) ----------------
__global__ void relu_final(float* __restrict__ out, const float* __restrict__ msg)
{
    long i = (long)blockIdx.x * blockDim.x + threadIdx.x;
    long stride = (long)gridDim.x * blockDim.x;
    for (; i < BND; i += stride) {
#pragma unroll
        for (int m = 0; m < 3; m++) {
            long o = (long)m * BND + i;
            float v = out[o] + msg[(long)(2 * m) * BND + i]
                             + msg[(long)(2 * m + 1) * BND + i];
            out[o] = fmaxf(v, 0.f);
        }
    }
}

// ---------------- launcher -------------------------------------------------
extern "C" void kernel_launch(void* const* d_in, const int* in_sizes, int n_in,
                              void* d_out, int out_size)
{
    const float* x[3]    = {(const float*)d_in[0], (const float*)d_in[1], (const float*)d_in[2]};
    const int*   hidx[3] = {(const int*)d_in[3], (const int*)d_in[4], (const int*)d_in[5]};
    const float* W_hg = (const float*)d_in[6];
    const float* att  = (const float*)d_in[7];
    const float* WQ = (const float*)d_in[8];
    const float* bQ = (const float*)d_in[9];
    const float* WK = (const float*)d_in[10];
    const float* bK = (const float*)d_in[11];
    const float* WV = (const float*)d_in[12];
    const float* bV = (const float*)d_in[13];
    const float* WO = (const float*)d_in[14];
    const float* bO = (const float*)d_in[15];
    float* out = (float*)d_out;

    static int smem_set = 0;
    if (!smem_set) {
        cudaFuncSetAttribute(gemm_lin, cudaFuncAttributeMaxDynamicSharedMemorySize, GEMM_SMEM);
        cudaFuncSetAttribute(gemm_qk,  cudaFuncAttributeMaxDynamicSharedMemorySize, GEMM_SMEM);
        cudaFuncSetAttribute(gemm_pv,  cudaFuncAttributeMaxDynamicSharedMemorySize, GEMM_SMEM);
        smem_set = 1;
    }

    float *xp, *h, *Q, *Kb, *Vb, *VT, *WT, *S6, *msg, *es, *xe, *ealpha, *p1, *p2;
    int *ncnt, *noff, *nlist, *ecnt, *eoff, *elist;
    cudaGetSymbolAddress((void**)&xp, g_xp);
    cudaGetSymbolAddress((void**)&h,  g_h);
    cudaGetSymbolAddress((void**)&Q,  g_Q);
    cudaGetSymbolAddress((void**)&Kb, g_Kb);
    cudaGetSymbolAddress((void**)&Vb, g_Vb);
    cudaGetSymbolAddress((void**)&VT, g_VT);
    cudaGetSymbolAddress((void**)&WT, g_WT);
    cudaGetSymbolAddress((void**)&S6, g_S6);
    cudaGetSymbolAddress((void**)&msg, g_msg);
    cudaGetSymbolAddress((void**)&es, g_es);
    cudaGetSymbolAddress((void**)&xe, g_xe);
    cudaGetSymbolAddress((void**)&ealpha, g_e);
    cudaGetSymbolAddress((void**)&p1, g_p1);
    cudaGetSymbolAddress((void**)&p2, g_p2);
    cudaGetSymbolAddress((void**)&ncnt, g_ncnt);
    cudaGetSymbolAddress((void**)&noff, g_noff);
    cudaGetSymbolAddress((void**)&nlist, g_nlist);
    cudaGetSymbolAddress((void**)&ecnt, g_ecnt);
    cudaGetSymbolAddress((void**)&eoff, g_eoff);
    cudaGetSymbolAddress((void**)&elist, g_elist);

    const int DD = Dd * Dd;

    // 0) weight transposes (tf32-rounded) + pre-round x into Q staging
    transpose_w5<<<dim3(8, 8, 5), dim3(32, 8)>>>(W_hg, WQ, WK, WV, WO, WT);
    round3_kernel<<<4096, 256>>>(x[0], x[1], x[2], Q);

    // 1) xp = x @ W_hg, all 3 modalities in one launch
    gemm_lin<<<dim3(2, 128, 3), 256, GEMM_SMEM>>>(Q, WT + 0 * DD, nullptr, xp,
                                                  Dd, Dd, BND, 0, BND, 1.f, 0, 0);

    // 2) CSR build (parallel, deterministic: lists sorted by c)
    zero_cnt_kernel<<<4, 1024>>>(ncnt, ecnt);
    csr_count_kernel<<<dim3(Cc / 256, 3), 256>>>(hidx[0], hidx[1], hidx[2], Nn, 0,  ncnt);
    csr_count_kernel<<<dim3(Cc / 256, 3), 256>>>(hidx[0], hidx[1], hidx[2], Mm, Cc, ecnt);
    csr_scan_kernel<<<3, 1024>>>(ncnt, noff, Nn);
    csr_scan_kernel<<<3, 1024>>>(ecnt, eoff, Mm);
    csr_fill_kernel<<<dim3(Nn / 8, 3), 256>>>(hidx[0], hidx[1], hidx[2], Nn, 0,  noff, nlist);
    csr_fill_kernel<<<dim3(Mm / 8, 3), 256>>>(hidx[0], hidx[1], hidx[2], Mm, Cc, eoff, elist);

    // 3-7) sparse hypergraph pipeline
    edge_sum_kernel<<<dim3(Mm, Bdim, 3), Dd>>>(xp, hidx[0], hidx[1], hidx[2],
                                               ecnt, eoff, elist, es);
    proj_kernel<<<dim3((Bdim * Nn + Mm * Bdim) / 8, 3), 256>>>(xp, es, att, p1, p2);
    logits_gather<<<dim3(Cc * Bdim / 256, 3), 256>>>(hidx[0], hidx[1], hidx[2],
                                                     p1, p2, ealpha);
    node_softmax<<<dim3(Nn, 3), 32>>>(ealpha, ncnt, noff, nlist);
    xedge_kernel<<<dim3(Mm, Bdim, 3), Dd>>>(xp, ealpha, hidx[0], hidx[1], hidx[2],
                                            ecnt, eoff, elist, xe);
    xnode_kernel<<<dim3(Nn, Bdim, 3), Dd>>>(xe, ealpha, hidx[0], hidx[1], hidx[2],
                                            ncnt, noff, nlist, h);

    // 8) projections; Q,K rounded for reuse as operands
    gemm_lin<<<dim3(2, 384, 1), 256, GEMM_SMEM>>>(h, WT + 1 * DD, bQ, Q,  Dd, Dd, 0, 0, 0, 1.f, 0, 1);
    gemm_lin<<<dim3(2, 384, 1), 256, GEMM_SMEM>>>(h, WT + 2 * DD, bK, Kb, Dd, Dd, 0, 0, 0, 1.f, 0, 1);
    gemm_lin<<<dim3(2, 384, 1), 256, GEMM_SMEM>>>(h, WT + 3 * DD, bV, Vb, Dd, Dd, 0, 0, 0, 1.f, 0, 0);
    gemm_lin<<<dim3(2, 384, 1), 256, GEMM_SMEM>>>(h, WT + 4 * DD, bO, out, Dd, Dd, 0, 0, 0, 1.f, 0, 0);

    // 8b) VT[z][d][n] = V[z][n][d] per (modality,batch) slice, tf32-rounded
    transpose_kernel<<<dim3(Dd / 32, Nn / 32, 48), dim3(32, 8)>>>(Vb, VT, Nn, Dd, ND, ND);

    // 9) cross-modal attention, all 6 pairs per stage in single launches
    gemm_qk<<<dim3(8, 8, 96), 256, GEMM_SMEM>>>(Q, Kb, S6);
    softmax_rows<<<6 * Bdim * Nn / 8, 256>>>(S6);
    gemm_pv<<<dim3(2, 8, 96), 256, GEMM_SMEM>>>(S6, VT, msg);

    // 10) final combine + relu
    relu_final<<<4096, 256>>>(out, msg);
}

// round 8
// speedup vs baseline: 4.7622x; 1.0233x over previous
#include <cuda_runtime.h>
#include <stdint.h>
#include <math.h>

// Problem constants
#define Bdim 16
#define Nn   1024
#define Dd   256
#define Mm   128
#define Cc   8192
#define NEG_SLOPE 0.2f
#define LOG2E 1.442695041f

#define BND (Bdim * Nn * Dd)                 // 4,194,304 (per modality)
#define ND  (Nn * Dd)                        // per-batch stride
#define NN2 (Nn * Nn)

#define GEMM_SMEM 98304                      // 3 stages x 32KB

// ---------------- scratch (device globals; no allocation) ----------------
__device__ float g_xp[3 * BND];              // projected inputs
__device__ float g_h [3 * BND];              // hypergraph outputs (tf32-rounded)
__device__ float g_Q [3 * BND];              // rounded-x staging
__device__ float g_pack[3L * Bdim * Nn * 1024];  // packed [Q|K|V|O] projections
__device__ float g_pb[1024];                 // packed bias
__device__ float g_VT[3 * BND];              // V transposed per (mod,batch), tf32-rounded
__device__ float g_WT[5 * Dd * Dd];          // W_hg,WQ,WK,WV,WO transposed+rounded
__device__ float g_S6[6L * Bdim * Nn * Nn];  // raw attention scores, all 6 pairs
__device__ float g_off[6 * Bdim * Nn];       // per-row softmax offset (log2 domain)
__device__ float g_msg[6L * BND];            // per-pair PV outputs
__device__ float g_es[3 * Mm * Bdim * Dd];
__device__ float g_xe[3 * Mm * Bdim * Dd];
__device__ float g_e [3 * Cc * Bdim];
__device__ float g_p1[3 * Bdim * Nn];        // dot(xp, att1)
__device__ float g_p2[3 * Mm * Bdim];        // dot(es, att2)
__device__ int   g_ncnt[3 * Nn], g_noff[3 * Nn], g_nlist[3 * Cc];
__device__ int   g_ecnt[3 * Mm], g_eoff[3 * Mm], g_elist[3 * Cc];

// ---------------- helpers -------------------------------------------------
__device__ __forceinline__ uint32_t smem_u32(const void* p) {
    uint32_t a;
    asm("{ .reg .u64 t; cvta.to.shared.u64 t, %1; cvt.u32.u64 %0, t; }"
        : "=r"(a) : "l"(p));
    return a;
}
__device__ __forceinline__ uint32_t swz128(uint32_t off) {
    return off ^ ((off >> 3) & 0x70);
}
__device__ __forceinline__ uint32_t rna_u(float x) {
    uint32_t r;
    asm("cvt.rna.tf32.f32 %0, %1;" : "=r"(r) : "f"(x));
    return r;
}
__device__ __forceinline__ float rna_f(float x) { return __uint_as_float(rna_u(x)); }
__device__ __forceinline__ float ex2f(float x) {
    float r; asm("ex2.approx.f32 %0, %1;" : "=f"(r) : "f"(x)); return r;
}
__device__ __forceinline__ float lg2f(float x) {
    float r; asm("lg2.approx.f32 %0, %1;" : "=f"(r) : "f"(x)); return r;
}

__device__ __forceinline__ void ldsm4(uint32_t* r, uint32_t addr) {
    asm volatile("ldmatrix.sync.aligned.m8n8.x4.shared.b16 {%0,%1,%2,%3}, [%4];"
        : "=r"(r[0]), "=r"(r[1]), "=r"(r[2]), "=r"(r[3]) : "r"(addr));
}
__device__ __forceinline__ void mma8(float* c, const uint32_t* a, const uint32_t* b) {
    asm volatile(
        "mma.sync.aligned.m16n8k8.row.col.f32.tf32.tf32.f32 "
        "{%0,%1,%2,%3}, {%4,%5,%6,%7}, {%8,%9}, {%0,%1,%2,%3};"
        : "+f"(c[0]), "+f"(c[1]), "+f"(c[2]), "+f"(c[3])
        : "r"(a[0]), "r"(a[1]), "r"(a[2]), "r"(a[3]), "r"(b[0]), "r"(b[1]));
}
__device__ __forceinline__ void cpasync16(uint32_t s, const void* g) {
    asm volatile("cp.async.cg.shared.global [%0], [%1], 16;" :: "r"(s), "l"(g));
}
__device__ __forceinline__ void cpcommit() {
    asm volatile("cp.async.commit_group;" ::: "memory");
}
template<int N>
__device__ __forceinline__ void cpwait() {
    asm volatile("cp.async.wait_group %0;" :: "n"(N) : "memory");
}

// ---------------- tf32 mma GEMM body (BK=32, 3-stage cp.async) -----------
// C[128,128]@(i0,j0) = alpha * A[.,K] @ B^T (+bias) (+C).
// A row-major [rows x Kext] pitch pitchA; B row-major [N x Kext] pitch pitchB.
// FE: A elements transformed p = rna(exp2(fma(a, LOG2E, off[row]))) while
// staging G->S (softmax applied on the fly); A path uses LDG+STS, B cp.async.
template<bool FE>
__device__ __forceinline__ void gemm_body(
    const float* __restrict__ A, const float* __restrict__ Bg,
    const float* __restrict__ bias, float* __restrict__ Cg,
    int Ncols, int pitchC, int Kext, int pitchA, int pitchB,
    int i0, int j0, float alpha, int accum, int rndC,
    const float* __restrict__ offs)
{
    extern __shared__ float smem[];

    const int tid = threadIdx.x, lane = tid & 31, wid = tid >> 5;
    const int wm = (wid & 1) * 64, wn = (wid >> 1) * 32;

    float acc[4][4][4];
#pragma unroll
    for (int i = 0; i < 4; i++)
#pragma unroll
        for (int j = 0; j < 4; j++)
#pragma unroll
            for (int c = 0; c < 4; c++) acc[i][j][c] = 0.f;

    const uint32_t base = smem_u32(smem);
    const uint32_t aoff = (uint32_t)((wm + (lane & 7) + (lane & 8)) * 128
                                     + ((lane >> 4) & 1) * 16);
    const uint32_t boff = (uint32_t)((wn + (lane & 7) + ((lane >> 4) & 1) * 8) * 128
                                     + ((lane >> 3) & 1) * 16);

    const int lr = tid >> 3, lkq = tid & 7;      // 32 rows/step, 8 quads/row
    uint32_t so[4];
#pragma unroll
    for (int q = 0; q < 4; q++)
        so[q] = swz128((lr + q * 32) * 128 + lkq * 16);
    const float* aG = A + (long)(i0 + lr) * pitchA + lkq * 4;
    const float* bG = Bg + (long)(j0 + lr) * pitchB + lkq * 4;
    const int nkt = Kext >> 5;

    auto issueB = [&](int kt) {
        const uint32_t sb = base + (uint32_t)(kt % 3) * 32768 + 16384;
        const long k0 = (long)(kt << 5);
#pragma unroll
        for (int q = 0; q < 4; q++)
            cpasync16(sb + so[q], bG + (long)(q * 32) * pitchB + k0);
        cpcommit();
    };
    auto issueAB = [&](int kt) {
        const uint32_t sb = base + (uint32_t)(kt % 3) * 32768;
        const long k0 = (long)(kt << 5);
#pragma unroll
        for (int q = 0; q < 4; q++)
            cpasync16(sb + so[q], aG + (long)(q * 32) * pitchA + k0);
#pragma unroll
        for (int q = 0; q < 4; q++)
            cpasync16(sb + 16384 + so[q], bG + (long)(q * 32) * pitchB + k0);
        cpcommit();
    };

    float offR[4];
    float4 ar[4];
    auto ldgA = [&](int kt) {
        const long k0 = (long)(kt << 5);
#pragma unroll
        for (int q = 0; q < 4; q++)
            ar[q] = *(const float4*)(aG + (long)(q * 32) * pitchA + k0);
    };
    auto stsA = [&](int kt) {
        const uint32_t sb = base + (uint32_t)(kt % 3) * 32768;
#pragma unroll
        for (int q = 0; q < 4; q++) {
            float4 v = ar[q];
            float o = offR[q];
            v.x = rna_f(ex2f(fmaf(v.x, LOG2E, o)));
            v.y = rna_f(ex2f(fmaf(v.y, LOG2E, o)));
            v.z = rna_f(ex2f(fmaf(v.z, LOG2E, o)));
            v.w = rna_f(ex2f(fmaf(v.w, LOG2E, o)));
            *(float4*)((char*)smem + (sb - base) + so[q]) = v;
        }
    };

    if (FE) {
#pragma unroll
        for (int q = 0; q < 4; q++) offR[q] = offs[i0 + lr + q * 32];
        ldgA(0);
        stsA(0);
        issueB(0);
        issueB(1);
    } else {
        issueAB(0);
        issueAB(1);
    }
    cpwait<1>();
    __syncthreads();

    for (int kt = 0; kt < nkt; kt++) {
        const uint32_t stb = base + (uint32_t)(kt % 3) * 32768;
        if (FE) {
            if (kt + 1 < nkt) ldgA(kt + 1);
            if (kt + 2 < nkt) issueB(kt + 2);
        } else {
            if (kt + 2 < nkt) issueAB(kt + 2);
        }

        const uint32_t sa = stb, sb = stb + 16384;
#pragma unroll
        for (int s = 0; s < 4; s++) {
            uint32_t af[4][4], bf[4][2];
#pragma unroll
            for (int mt = 0; mt < 4; mt++)
                ldsm4(af[mt], sa + swz128(aoff + mt * 2048 + s * 32));
#pragma unroll
            for (int p = 0; p < 2; p++) {
                uint32_t r[4];
                ldsm4(r, sb + swz128(boff + p * 2048 + s * 32));
                bf[2 * p][0] = r[0]; bf[2 * p][1] = r[1];
                bf[2 * p + 1][0] = r[2]; bf[2 * p + 1][1] = r[3];
            }
#pragma unroll
            for (int mt = 0; mt < 4; mt++)
#pragma unroll
                for (int nt = 0; nt < 4; nt++)
                    mma8(acc[mt][nt], af[mt], bf[nt]);
        }

        if (kt + 1 < nkt) {
            if (FE) stsA(kt + 1);
            if (kt + 2 < nkt) cpwait<1>(); else cpwait<0>();
            __syncthreads();
        }
    }

    // epilogue
#pragma unroll
    for (int mt = 0; mt < 4; mt++) {
        int row = i0 + wm + mt * 16 + (lane >> 2);
#pragma unroll
        for (int nt = 0; nt < 4; nt++) {
            int col = j0 + wn + nt * 8 + (lane & 3) * 2;
            float bb0 = 0.f, bb1 = 0.f;
            if (bias) { bb0 = bias[col]; bb1 = bias[col + 1]; }
            long p0 = (long)row * pitchC + col;
            long p1 = (long)(row + 8) * pitchC + col;
            float v0 = acc[mt][nt][0] * alpha + bb0;
            float v1 = acc[mt][nt][1] * alpha + bb1;
            float v2 = acc[mt][nt][2] * alpha + bb0;
            float v3 = acc[mt][nt][3] * alpha + bb1;
            if (accum) {
                float2 c0 = *(float2*)&Cg[p0];
                float2 c1 = *(float2*)&Cg[p1];
                v0 += c0.x; v1 += c0.y; v2 += c1.x; v3 += c1.y;
            }
            if (rndC) { v0 = rna_f(v0); v1 = rna_f(v1); v2 = rna_f(v2); v3 = rna_f(v3); }
            *(float2*)&Cg[p0] = make_float2(v0, v1);
            *(float2*)&Cg[p1] = make_float2(v2, v3);
        }
    }
}

// generic strided wrapper (plain path)
__global__ __launch_bounds__(256, 2)
void gemm_lin(const float* __restrict__ A, const float* __restrict__ Bg,
              const float* __restrict__ bias, float* __restrict__ Cg,
              int Ncols, int pitchC, int Kext, int pitchA, int pitchB,
              long sA, long sB, long sC, float alpha, int accum, int rndC)
{
    gemm_body<false>(A + (long)blockIdx.z * sA, Bg + (long)blockIdx.z * sB, bias,
                     Cg + (long)blockIdx.z * sC, Ncols, pitchC, Kext, pitchA, pitchB,
                     blockIdx.y * 128, blockIdx.x * 128, alpha, accum, rndC, nullptr);
}

// QK^T for all 6 (m,n) pairs: z = p*16 + b. Q/K live in packed buffer.
__global__ __launch_bounds__(256, 2)
void gemm_qk(const float* __restrict__ pack, float* __restrict__ S6)
{
    int z = blockIdx.z, p = z >> 4, b = z & 15, m = p >> 1, j = p & 1;
    int n = j + (j >= m);
    const float* Qp = pack + ((long)m * (Bdim * Nn) + b * Nn) * 1024;
    const float* Kp = pack + ((long)n * (Bdim * Nn) + b * Nn) * 1024 + 256;
    gemm_body<false>(Qp, Kp, nullptr, S6 + ((long)p * 16 + b) * NN2,
                     Nn, Nn, Dd, 1024, 1024,
                     blockIdx.y * 128, blockIdx.x * 128, 0.0625f, 0, 0, nullptr);
}

// PV for all 6 pairs with fused softmax (exp applied in A staging path)
__global__ __launch_bounds__(256)
void gemm_pv(const float* __restrict__ S6, const float* __restrict__ off,
             const float* __restrict__ VT, float* __restrict__ msg)
{
    int z = blockIdx.z, p = z >> 4, b = z & 15, m = p >> 1, j = p & 1;
    int n = j + (j >= m);
    gemm_body<true>(S6 + ((long)p * 16 + b) * NN2,
                    VT + (long)n * BND + (long)b * ND, nullptr,
                    msg + (long)p * BND + (long)b * ND,
                    Dd, Dd, Nn, 1024, 1024,
                    blockIdx.y * 128, blockIdx.x * 128, 1.f, 0, 0,
                    off + ((long)p * 16 + b) * Nn);
}

// ---------------- row stats: off = -(max*LOG2E + log2(sum exp)) ----------
__global__ void row_stats(const float* __restrict__ S, float* __restrict__ off)
{
    long row = (long)blockIdx.x * 8 + (threadIdx.x >> 5);
    int lane = threadIdx.x & 31;
    const float* p = S + row * 1024;
    float v[32];
    float mx = -1e30f;
#pragma unroll
    for (int i = 0; i < 32; i++) {
        v[i] = p[lane + 32 * i];
        mx = fmaxf(mx, v[i]);
    }
#pragma unroll
    for (int o = 16; o; o >>= 1) mx = fmaxf(mx, __shfl_xor_sync(0xffffffffu, mx, o));
    float s = 0.f;
#pragma unroll
    for (int i = 0; i < 32; i++) s += ex2f((v[i] - mx) * LOG2E);
#pragma unroll
    for (int o = 16; o; o >>= 1) s += __shfl_xor_sync(0xffffffffu, s, o);
    if (lane == 0) off[row] = -(mx * LOG2E + lg2f(s));
}

// ---------------- pre-round x to tf32 ------------------------------------
__global__ void round3_kernel(const float* __restrict__ a, const float* __restrict__ b,
                              const float* __restrict__ c, float* __restrict__ dst)
{
    long i = (long)blockIdx.x * blockDim.x + threadIdx.x;
    long stride = (long)gridDim.x * blockDim.x;
    for (; i < BND; i += stride) {
        dst[i]            = rna_f(a[i]);
        dst[BND + i]      = rna_f(b[i]);
        dst[2L * BND + i] = rna_f(c[i]);
    }
}

// ---------------- transpose (dst[C][R] = src[R][C]), tf32-rounded ---------
__global__ void transpose_kernel(const float* __restrict__ src, float* __restrict__ dst,
                                 int R, int C, int srcPitch, long sS, long sD)
{
    __shared__ float t[32][33];
    src += (long)blockIdx.z * sS;
    dst += (long)blockIdx.z * sD;
    int c = blockIdx.x * 32 + threadIdx.x;
    int r0 = blockIdx.y * 32;
    for (int j = threadIdx.y; j < 32; j += 8)
        t[j][threadIdx.x] = src[(long)(r0 + j) * srcPitch + c];
    __syncthreads();
    int rr = blockIdx.y * 32 + threadIdx.x;
    int cc0 = blockIdx.x * 32;
    for (int j = threadIdx.y; j < 32; j += 8)
        dst[(long)(cc0 + j) * R + rr] = rna_f(t[threadIdx.x][j]);
}

// 5 weight transposes in one launch (z selects matrix)
__global__ void transpose_w5(const float* w0, const float* w1, const float* w2,
                             const float* w3, const float* w4, float* __restrict__ dst)
{
    __shared__ float t[32][33];
    const float* src = (blockIdx.z == 0) ? w0 : (blockIdx.z == 1) ? w1 :
                       (blockIdx.z == 2) ? w2 : (blockIdx.z == 3) ? w3 : w4;
    dst += (long)blockIdx.z * Dd * Dd;
    int c = blockIdx.x * 32 + threadIdx.x;
    int r0 = blockIdx.y * 32;
    for (int j = threadIdx.y; j < 32; j += 8)
        t[j][threadIdx.x] = src[(long)(r0 + j) * Dd + c];
    __syncthreads();
    int rr = blockIdx.y * 32 + threadIdx.x;
    int cc0 = blockIdx.x * 32;
    for (int j = threadIdx.y; j < 32; j += 8)
        dst[(long)(cc0 + j) * Dd + rr] = rna_f(t[threadIdx.x][j]);
}

// packed bias [bQ|bK|bV|bO]
__global__ void pack_bias(const float* q, const float* k, const float* v,
                          const float* o, float* __restrict__ pb)
{
    int i = blockIdx.x * 256 + threadIdx.x;
    const float* s = (i < 256) ? q : (i < 512) ? k : (i < 768) ? v : o;
    pb[i] = s[i & 255];
}

// ---------------- fast deterministic CSR build ----------------------------
__global__ void zero_cnt_kernel(int* ncnt, int* ecnt)
{
    int i = blockIdx.x * blockDim.x + threadIdx.x;
    if (i < 3 * Nn) ncnt[i] = 0;
    if (i < 3 * Mm) ecnt[i] = 0;
}

__global__ void csr_count_kernel(const int* __restrict__ i0, const int* __restrict__ i1,
                                 const int* __restrict__ i2, int cnt_stride, int edge_off,
                                 int* __restrict__ cnt)
{
    const int* idx = (blockIdx.y == 0) ? i0 : (blockIdx.y == 1) ? i1 : i2;
    int c = blockIdx.x * blockDim.x + threadIdx.x;
    atomicAdd(&cnt[blockIdx.y * cnt_stride + idx[edge_off + c]], 1);
}

__global__ void csr_scan_kernel(const int* __restrict__ cnt, int* __restrict__ off, int nseg)
{
    __shared__ int buf[1024];
    int tid = threadIdx.x;
    int v = (tid < nseg) ? cnt[blockIdx.x * nseg + tid] : 0;
    buf[tid] = v;
    __syncthreads();
    for (int o = 1; o < nseg; o <<= 1) {
        int t = (tid >= o) ? buf[tid - o] : 0;
        __syncthreads();
        buf[tid] += t;
        __syncthreads();
    }
    if (tid < nseg) off[blockIdx.x * nseg + tid] = buf[tid] - v;
}

__global__ void csr_fill_kernel(const int* __restrict__ i0, const int* __restrict__ i1,
                                const int* __restrict__ i2, int nseg, int edge_off,
                                const int* __restrict__ off, int* __restrict__ list)
{
    __shared__ int sidx[Cc];
    const int* idx = (blockIdx.y == 0) ? i0 : (blockIdx.y == 1) ? i1 : i2;
    int tid = threadIdx.x;
    for (int i = tid; i < Cc; i += blockDim.x) sidx[i] = idx[edge_off + i];
    __syncthreads();

    int w = tid >> 5, lane = tid & 31;
    int s = blockIdx.x * 8 + w;
    if (s >= nseg) return;
    int p = off[blockIdx.y * nseg + s];
    int* lst = list + blockIdx.y * Cc;
    for (int c0 = 0; c0 < Cc; c0 += 32) {
        int c = c0 + lane;
        bool m = (sidx[c] == s);
        unsigned bal = __ballot_sync(0xffffffffu, m);
        if (m) lst[p + __popc(bal & ((1u << lane) - 1u))] = c;
        p += __popc(bal);
    }
}

// ---------------- sparse stage kernels (z = modality) ---------------------
__global__ void edge_sum_kernel(const float* __restrict__ xp,
                                const int* __restrict__ h0, const int* __restrict__ h1,
                                const int* __restrict__ h2,
                                const int* __restrict__ ecnt, const int* __restrict__ eoff,
                                const int* __restrict__ elist, float* __restrict__ es)
{
    int mmod = blockIdx.z;
    const int* hidx = (mmod == 0) ? h0 : (mmod == 1) ? h1 : h2;
    xp += (long)mmod * BND;
    es += (long)mmod * Mm * Bdim * Dd;
    ecnt += mmod * Mm; eoff += mmod * Mm; elist += mmod * Cc;

    int e = blockIdx.x, b = blockIdx.y, d = threadIdx.x;
    int cnt = ecnt[e], off = eoff[e];
    float s = 0.f;
    for (int i = 0; i < cnt; i++) {
        int c = elist[off + i];
        int node = hidx[c];
        s += xp[((long)b * Nn + node) * Dd + d];
    }
    es[((long)e * Bdim + b) * Dd + d] = s;
}

// proj: p1[mod][row] = dot(xp[row,:], att[0:D]); p2 for es rows
__global__ void proj_kernel(const float* __restrict__ xp, const float* __restrict__ es,
                            const float* __restrict__ att,
                            float* __restrict__ p1, float* __restrict__ p2)
{
    int mmod = blockIdx.y;
    int row = blockIdx.x * 8 + (threadIdx.x >> 5);
    int lane = threadIdx.x & 31;
    const float* src;
    const float* a;
    if (row < Bdim * Nn) {
        src = xp + (long)mmod * BND + (long)row * Dd;
        a = att;
    } else {
        src = es + (long)mmod * Mm * Bdim * Dd + (long)(row - Bdim * Nn) * Dd;
        a = att + Dd;
    }
    float s = 0.f;
#pragma unroll
    for (int i = 0; i < Dd / 32; i++) {
        int d = lane + 32 * i;
        s += src[d] * a[d];
    }
#pragma unroll
    for (int o = 16; o; o >>= 1) s += __shfl_xor_sync(0xffffffffu, s, o);
    if (lane == 0) {
        if (row < Bdim * Nn) p1[mmod * Bdim * Nn + row] = s;
        else                 p2[mmod * Mm * Bdim + row - Bdim * Nn] = s;
    }
}

__global__ void logits_gather(const int* __restrict__ h0, const int* __restrict__ h1,
                              const int* __restrict__ h2,
                              const float* __restrict__ p1, const float* __restrict__ p2,
                              float* __restrict__ e_out)
{
    int mmod = blockIdx.y;
    const int* hidx = (mmod == 0) ? h0 : (mmod == 1) ? h1 : h2;
    int i = blockIdx.x * blockDim.x + threadIdx.x;
    int c = i >> 4, b = i & 15;
    float v = p1[mmod * Bdim * Nn + b * Nn + hidx[c]]
            + p2[mmod * Mm * Bdim + hidx[Cc + c] * Bdim + b];
    e_out[(long)mmod * Cc * Bdim + i] = (v >= 0.f) ? v : NEG_SLOPE * v;
}

__global__ void node_softmax(float* __restrict__ e, const int* __restrict__ ncnt,
                             const int* __restrict__ noff, const int* __restrict__ nlist)
{
    int mmod = blockIdx.y;
    e += (long)mmod * Cc * Bdim;
    ncnt += mmod * Nn; noff += mmod * Nn; nlist += mmod * Cc;

    int n = blockIdx.x, b = threadIdx.x;
    if (b >= Bdim) return;
    int cnt = ncnt[n];
    if (!cnt) return;
    int off = noff[n];
    float mx = -1e30f;
    for (int i = 0; i < cnt; i++) {
        int c = nlist[off + i];
        mx = fmaxf(mx, e[c * Bdim + b]);
    }
    float sum = 0.f;
    for (int i = 0; i < cnt; i++) {
        int c = nlist[off + i];
        float v = expf(e[c * Bdim + b] - mx);
        e[c * Bdim + b] = v;
        sum += v;
    }
    float inv = 1.f / (sum + 1e-16f);
    for (int i = 0; i < cnt; i++) {
        int c = nlist[off + i];
        e[c * Bdim + b] *= inv;
    }
}

__global__ void xedge_kernel(const float* __restrict__ xp, const float* __restrict__ alpha,
                             const int* __restrict__ h0, const int* __restrict__ h1,
                             const int* __restrict__ h2,
                             const int* __restrict__ ecnt, const int* __restrict__ eoff,
                             const int* __restrict__ elist, float* __restrict__ xe)
{
    int mmod = blockIdx.z;
    const int* hidx = (mmod == 0) ? h0 : (mmod == 1) ? h1 : h2;
    xp += (long)mmod * BND;
    alpha += (long)mmod * Cc * Bdim;
    xe += (long)mmod * Mm * Bdim * Dd;
    ecnt += mmod * Mm; eoff += mmod * Mm; elist += mmod * Cc;

    int e = blockIdx.x, b = blockIdx.y, d = threadIdx.x;
    int cnt = ecnt[e];
    float s = 0.f;
    if (cnt) {
        int off = eoff[e];
        for (int i = 0; i < cnt; i++) {
            int c = elist[off + i];
            int node = hidx[c];
            s += alpha[c * Bdim + b] * xp[((long)b * Nn + node) * Dd + d];
        }
        s /= (float)cnt;
    }
    xe[((long)e * Bdim + b) * Dd + d] = s;
}

__global__ void xnode_kernel(const float* __restrict__ xe, const float* __restrict__ alpha,
                             const int* __restrict__ h0, const int* __restrict__ h1,
                             const int* __restrict__ h2,
                             const int* __restrict__ ncnt, const int* __restrict__ noff,
                             const int* __restrict__ nlist, float* __restrict__ h)
{
    int mmod = blockIdx.z;
    const int* hidx = (mmod == 0) ? h0 : (mmod == 1) ? h1 : h2;
    xe += (long)mmod * Mm * Bdim * Dd;
    alpha += (long)mmod * Cc * Bdim;
    h += (long)mmod * BND;
    ncnt += mmod * Nn; noff += mmod * Nn; nlist += mmod * Cc;

    int n = blockIdx.x, b = blockIdx.y, d = threadIdx.x;
    int cnt = ncnt[n];
    float s = 0.f;
    if (cnt) {
        int off = noff[n];
        for (int i = 0; i < cnt; i++) {
            int c = nlist[off + i];
            int eidx = hidx[Cc + c];
            s += alpha[c * Bdim + b] * xe[((long)eidx * Bdim + b) * Dd + d];
        }
        s /= (float)cnt;
    }
    h[((long)b * Nn + n) * Dd + d] = rna_f(s);
}

// ---------------- out = relu(base(pack col 768+) + msg0 + msg1) -----------
__global__ void relu_final(float* __restrict__ out, const float* __restrict__ pack,
                           const float* __restrict__ msg)
{
    long i = (long)blockIdx.x * blockDim.x + threadIdx.x;
    long stride = (long)gridDim.x * blockDim.x;
    for (; i < BND; i += stride) {
        long r = i >> 8;
        int d = (int)(i & 255);
#pragma unroll
        for (int m = 0; m < 3; m++) {
            float v = pack[((long)m * (Bdim * Nn) + r) * 1024 + 768 + d]
                    + msg[(long)(2 * m) * BND + i]
                    + msg[(long)(2 * m + 1) * BND + i];
            out[(long)m * BND + i] = fmaxf(v, 0.f);
        }
    }
}

// ---------------- launcher -------------------------------------------------
extern "C" void kernel_launch(void* const* d_in, const int* in_sizes, int n_in,
                              void* d_out, int out_size)
{
    const float* x[3]    = {(const float*)d_in[0], (const float*)d_in[1], (const float*)d_in[2]};
    const int*   hidx[3] = {(const int*)d_in[3], (const int*)d_in[4], (const int*)d_in[5]};
    const float* W_hg = (const float*)d_in[6];
    const float* att  = (const float*)d_in[7];
    const float* WQ = (const float*)d_in[8];
    const float* bQ = (const float*)d_in[9];
    const float* WK = (const float*)d_in[10];
    const float* bK = (const float*)d_in[11];
    const float* WV = (const float*)d_in[12];
    const float* bV = (const float*)d_in[13];
    const float* WO = (const float*)d_in[14];
    const float* bO = (const float*)d_in[15];
    float* out = (float*)d_out;

    static int smem_set = 0;
    if (!smem_set) {
        cudaFuncSetAttribute(gemm_lin, cudaFuncAttributeMaxDynamicSharedMemorySize, GEMM_SMEM);
        cudaFuncSetAttribute(gemm_qk,  cudaFuncAttributeMaxDynamicSharedMemorySize, GEMM_SMEM);
        cudaFuncSetAttribute(gemm_pv,  cudaFuncAttributeMaxDynamicSharedMemorySize, GEMM_SMEM);
        smem_set = 1;
    }

    float *xp, *h, *Q, *pack, *pb, *VT, *WT, *S6, *offb, *msg, *es, *xe, *ealpha, *p1, *p2;
    int *ncnt, *noff, *nlist, *ecnt, *eoff, *elist;
    cudaGetSymbolAddress((void**)&xp, g_xp);
    cudaGetSymbolAddress((void**)&h,  g_h);
    cudaGetSymbolAddress((void**)&Q,  g_Q);
    cudaGetSymbolAddress((void**)&pack, g_pack);
    cudaGetSymbolAddress((void**)&pb, g_pb);
    cudaGetSymbolAddress((void**)&VT, g_VT);
    cudaGetSymbolAddress((void**)&WT, g_WT);
    cudaGetSymbolAddress((void**)&S6, g_S6);
    cudaGetSymbolAddress((void**)&offb, g_off);
    cudaGetSymbolAddress((void**)&msg, g_msg);
    cudaGetSymbolAddress((void**)&es, g_es);
    cudaGetSymbolAddress((void**)&xe, g_xe);
    cudaGetSymbolAddress((void**)&ealpha, g_e);
    cudaGetSymbolAddress((void**)&p1, g_p1);
    cudaGetSymbolAddress((void**)&p2, g_p2);
    cudaGetSymbolAddress((void**)&ncnt, g_ncnt);
    cudaGetSymbolAddress((void**)&noff, g_noff);
    cudaGetSymbolAddress((void**)&nlist, g_nlist);
    cudaGetSymbolAddress((void**)&ecnt, g_ecnt);
    cudaGetSymbolAddress((void**)&eoff, g_eoff);
    cudaGetSymbolAddress((void**)&elist, g_elist);

    const int DD = Dd * Dd;

    // 0) weight transposes (tf32-rounded) + pre-round x + packed bias
    transpose_w5<<<dim3(8, 8, 5), dim3(32, 8)>>>(W_hg, WQ, WK, WV, WO, WT);
    round3_kernel<<<4096, 256>>>(x[0], x[1], x[2], Q);
    pack_bias<<<4, 256>>>(bQ, bK, bV, bO, pb);

    // 1) xp = x @ W_hg, all 3 modalities
    gemm_lin<<<dim3(2, 128, 3), 256, GEMM_SMEM>>>(Q, WT, nullptr, xp,
                                                  Dd, Dd, Dd, Dd, Dd,
                                                  BND, 0, BND, 1.f, 0, 0);

    // 2) CSR build (parallel, deterministic: lists sorted by c)
    zero_cnt_kernel<<<4, 1024>>>(ncnt, ecnt);
    csr_count_kernel<<<dim3(Cc / 256, 3), 256>>>(hidx[0], hidx[1], hidx[2], Nn, 0,  ncnt);
    csr_count_kernel<<<dim3(Cc / 256, 3), 256>>>(hidx[0], hidx[1], hidx[2], Mm, Cc, ecnt);
    csr_scan_kernel<<<3, 1024>>>(ncnt, noff, Nn);
    csr_scan_kernel<<<3, 1024>>>(ecnt, eoff, Mm);
    csr_fill_kernel<<<dim3(Nn / 8, 3), 256>>>(hidx[0], hidx[1], hidx[2], Nn, 0,  noff, nlist);
    csr_fill_kernel<<<dim3(Mm / 8, 3), 256>>>(hidx[0], hidx[1], hidx[2], Mm, Cc, eoff, elist);

    // 3-7) sparse hypergraph pipeline
    edge_sum_kernel<<<dim3(Mm, Bdim, 3), Dd>>>(xp, hidx[0], hidx[1], hidx[2],
                                               ecnt, eoff, elist, es);
    proj_kernel<<<dim3((Bdim * Nn + Mm * Bdim) / 8, 3), 256>>>(xp, es, att, p1, p2);
    logits_gather<<<dim3(Cc * Bdim / 256, 3), 256>>>(hidx[0], hidx[1], hidx[2],
                                                     p1, p2, ealpha);
    node_softmax<<<dim3(Nn, 3), 32>>>(ealpha, ncnt, noff, nlist);
    xedge_kernel<<<dim3(Mm, Bdim, 3), Dd>>>(xp, ealpha, hidx[0], hidx[1], hidx[2],
                                            ecnt, eoff, elist, xe);
    xnode_kernel<<<dim3(Nn, Bdim, 3), Dd>>>(xe, ealpha, hidx[0], hidx[1], hidx[2],
                                            ncnt, noff, nlist, h);

    // 8) fused Q|K|V|O projections: [49152,256] @ [256,1024] -> packed
    gemm_lin<<<dim3(8, 384, 1), 256, GEMM_SMEM>>>(h, WT + DD, pb, pack,
                                                  1024, 1024, Dd, Dd, Dd,
                                                  0, 0, 0, 1.f, 0, 1);

    // 8b) VT[z][d][n] from pack V columns (pitch 1024), tf32-rounded
    transpose_kernel<<<dim3(Dd / 32, Nn / 32, 48), dim3(32, 8)>>>(
        pack + 512, VT, Nn, Dd, 1024, (long)Nn * 1024, ND);

    // 9) cross-modal attention: QK^T -> row stats -> PV with fused softmax
    gemm_qk<<<dim3(8, 8, 96), 256, GEMM_SMEM>>>(pack, S6);
    row_stats<<<6 * Bdim * Nn / 8, 256>>>(S6, offb);
    gemm_pv<<<dim3(2, 8, 96), 256, GEMM_SMEM>>>(S6, offb, VT, msg);

    // 10) final combine + relu
    relu_final<<<4096, 256>>>(out, pack, msg);
}